// round 1
// baseline (speedup 1.0000x reference)
#include <cuda_runtime.h>
#include <math.h>

// Problem dims (fixed by the dataset)
#define B_    16
#define L_    256
#define DM    1024
#define DI    1024
#define DTR   64
#define BL    (B_ * L_)      // 4096 rows
#define DBLW  68             // dtr + 2*n = 64 + 4

// ---------------- scratch (static device globals; no allocation allowed) ---
__device__ float g_xz [BL * 2 * DI];   // 33.5 MB : [x_inner | z]
__device__ float g_xi [BL * DI];       // conv+silu output
__device__ float g_dbl[BL * DBLW];     // xi @ Wx^T  (dt_raw | B | C)
__device__ float g_dt [BL * DI];       // softplus(dt_raw @ Wdt^T + bdt)
__device__ float g_y  [BL * DI];       // scan output (pre-Wout)
__device__ float g_bufA[BL * DM];
__device__ float g_bufB[BL * DM];
__device__ float g_bufC[BL * DM];

// ---------------- epilogue modes ------------------------------------------
#define EPI_NONE          0
#define EPI_SILU          1
#define EPI_BIAS_SILU     2
#define EPI_BIAS_SOFTPLUS 3

__device__ __forceinline__ float silu_f(float x) { return x / (1.0f + expf(-x)); }

// ===========================================================================
// Generic NT GEMM: C[M,N] = epi( A[M,K] @ B[N,K]^T + bias[n] )
// A: lda (K contiguous), B: ldb (K contiguous), C: ldc.
// Tiles 64x64x16, 256 threads, 4x4 per thread, float4 smem staging.
// Requires K % 16 == 0, lda/ldb % 4 == 0 (true for all call sites).
// ===========================================================================
template <int EPI>
__global__ void __launch_bounds__(256) gemm_nt(
    const float* __restrict__ A, const float* __restrict__ B,
    const float* __restrict__ bias, float* __restrict__ C,
    int M, int N, int K, int lda, int ldb, int ldc)
{
    __shared__ float As[16][68];
    __shared__ float Bs[16][68];

    const int tid = threadIdx.x;
    const int tx  = tid & 15;      // 0..15  -> N direction
    const int ty  = tid >> 4;      // 0..15  -> M direction
    const int bm  = blockIdx.y * 64;
    const int bn  = blockIdx.x * 64;
    const int lrow  = tid >> 2;          // 0..63
    const int lcol  = (tid & 3) << 2;    // 0,4,8,12

    float acc[4][4];
#pragma unroll
    for (int i = 0; i < 4; i++)
#pragma unroll
        for (int j = 0; j < 4; j++) acc[i][j] = 0.0f;

    for (int k0 = 0; k0 < K; k0 += 16) {
        float4 av = make_float4(0.f, 0.f, 0.f, 0.f);
        float4 bv = make_float4(0.f, 0.f, 0.f, 0.f);
        const int am = bm + lrow;
        if (am < M) av = *(const float4*)(A + (size_t)am * lda + k0 + lcol);
        const int bnr = bn + lrow;
        if (bnr < N) bv = *(const float4*)(B + (size_t)bnr * ldb + k0 + lcol);

        As[lcol + 0][lrow] = av.x; As[lcol + 1][lrow] = av.y;
        As[lcol + 2][lrow] = av.z; As[lcol + 3][lrow] = av.w;
        Bs[lcol + 0][lrow] = bv.x; Bs[lcol + 1][lrow] = bv.y;
        Bs[lcol + 2][lrow] = bv.z; Bs[lcol + 3][lrow] = bv.w;
        __syncthreads();

#pragma unroll
        for (int k = 0; k < 16; k++) {
            const float4 ra = *(const float4*)&As[k][ty << 2];
            const float4 rb = *(const float4*)&Bs[k][tx << 2];
            const float a0 = ra.x, a1 = ra.y, a2 = ra.z, a3 = ra.w;
            const float b0 = rb.x, b1 = rb.y, b2 = rb.z, b3 = rb.w;
            acc[0][0] = fmaf(a0, b0, acc[0][0]); acc[0][1] = fmaf(a0, b1, acc[0][1]);
            acc[0][2] = fmaf(a0, b2, acc[0][2]); acc[0][3] = fmaf(a0, b3, acc[0][3]);
            acc[1][0] = fmaf(a1, b0, acc[1][0]); acc[1][1] = fmaf(a1, b1, acc[1][1]);
            acc[1][2] = fmaf(a1, b2, acc[1][2]); acc[1][3] = fmaf(a1, b3, acc[1][3]);
            acc[2][0] = fmaf(a2, b0, acc[2][0]); acc[2][1] = fmaf(a2, b1, acc[2][1]);
            acc[2][2] = fmaf(a2, b2, acc[2][2]); acc[2][3] = fmaf(a2, b3, acc[2][3]);
            acc[3][0] = fmaf(a3, b0, acc[3][0]); acc[3][1] = fmaf(a3, b1, acc[3][1]);
            acc[3][2] = fmaf(a3, b2, acc[3][2]); acc[3][3] = fmaf(a3, b3, acc[3][3]);
        }
        __syncthreads();
    }

#pragma unroll
    for (int i = 0; i < 4; i++) {
        const int m = bm + (ty << 2) + i;
        if (m >= M) continue;
#pragma unroll
        for (int j = 0; j < 4; j++) {
            const int n = bn + (tx << 2) + j;
            if (n >= N) continue;
            float v = acc[i][j];
            if (EPI == EPI_BIAS_SILU || EPI == EPI_BIAS_SOFTPLUS) v += bias[n];
            if (EPI == EPI_SILU || EPI == EPI_BIAS_SILU) v = v / (1.0f + expf(-v));
            if (EPI == EPI_BIAS_SOFTPLUS) v = (v > 20.0f) ? v : log1pf(expf(v));
            C[(size_t)m * ldc + n] = v;
        }
    }
}

// ===========================================================================
// Batched NN GEMM (channel mix): C[z][o,s] = epi( sum_c W[o,c] * X[z][c,s] )
// W: M x K (K contig). X: K x N per batch (N contig). C: M x N per batch.
// ===========================================================================
template <int EPI>
__global__ void __launch_bounds__(256) gemm_nn_batched(
    const float* __restrict__ W, const float* __restrict__ X,
    float* __restrict__ C,
    int M, int N, int K, long strideX, long strideC)
{
    const float* Xb = X + (size_t)blockIdx.z * strideX;
    float*       Cb = C + (size_t)blockIdx.z * strideC;

    __shared__ float As[16][68];
    __shared__ float Bs[16][68];

    const int tid = threadIdx.x;
    const int tx  = tid & 15;
    const int ty  = tid >> 4;
    const int bm  = blockIdx.y * 64;
    const int bn  = blockIdx.x * 64;
    const int lrow = tid >> 2;
    const int lcol = (tid & 3) << 2;
    const int xk  = tid >> 4;          // 0..15
    const int xn  = (tid & 15) << 2;   // 0..60

    float acc[4][4];
#pragma unroll
    for (int i = 0; i < 4; i++)
#pragma unroll
        for (int j = 0; j < 4; j++) acc[i][j] = 0.0f;

    for (int k0 = 0; k0 < K; k0 += 16) {
        float4 av = make_float4(0.f, 0.f, 0.f, 0.f);
        const int am = bm + lrow;
        if (am < M) av = *(const float4*)(W + (size_t)am * K + k0 + lcol);
        As[lcol + 0][lrow] = av.x; As[lcol + 1][lrow] = av.y;
        As[lcol + 2][lrow] = av.z; As[lcol + 3][lrow] = av.w;

        float4 xv = make_float4(0.f, 0.f, 0.f, 0.f);
        const int gn = bn + xn;
        if (gn < N) xv = *(const float4*)(Xb + (size_t)(k0 + xk) * N + gn);
        *(float4*)&Bs[xk][xn] = xv;
        __syncthreads();

#pragma unroll
        for (int k = 0; k < 16; k++) {
            const float4 ra = *(const float4*)&As[k][ty << 2];
            const float4 rb = *(const float4*)&Bs[k][tx << 2];
            const float a0 = ra.x, a1 = ra.y, a2 = ra.z, a3 = ra.w;
            const float b0 = rb.x, b1 = rb.y, b2 = rb.z, b3 = rb.w;
            acc[0][0] = fmaf(a0, b0, acc[0][0]); acc[0][1] = fmaf(a0, b1, acc[0][1]);
            acc[0][2] = fmaf(a0, b2, acc[0][2]); acc[0][3] = fmaf(a0, b3, acc[0][3]);
            acc[1][0] = fmaf(a1, b0, acc[1][0]); acc[1][1] = fmaf(a1, b1, acc[1][1]);
            acc[1][2] = fmaf(a1, b2, acc[1][2]); acc[1][3] = fmaf(a1, b3, acc[1][3]);
            acc[2][0] = fmaf(a2, b0, acc[2][0]); acc[2][1] = fmaf(a2, b1, acc[2][1]);
            acc[2][2] = fmaf(a2, b2, acc[2][2]); acc[2][3] = fmaf(a2, b3, acc[2][3]);
            acc[3][0] = fmaf(a3, b0, acc[3][0]); acc[3][1] = fmaf(a3, b1, acc[3][1]);
            acc[3][2] = fmaf(a3, b2, acc[3][2]); acc[3][3] = fmaf(a3, b3, acc[3][3]);
        }
        __syncthreads();
    }

#pragma unroll
    for (int i = 0; i < 4; i++) {
        const int m = bm + (ty << 2) + i;
        if (m >= M) continue;
#pragma unroll
        for (int j = 0; j < 4; j++) {
            const int n = bn + (tx << 2) + j;
            if (n >= N) continue;
            float v = acc[i][j];
            if (EPI == EPI_SILU) v = v / (1.0f + expf(-v));
            Cb[(size_t)m * N + n] = v;
        }
    }
}

// ===========================================================================
// Depthwise causal conv (k=4) along L + bias + silu.
// xz layout [b, t, 2*DI] (x in first DI). Output xi [b, t, DI].
// One thread per (b, d).
// ===========================================================================
__global__ void conv_silu_kernel(const float* __restrict__ xz,
                                 const float* __restrict__ w,
                                 const float* __restrict__ cb,
                                 float* __restrict__ xi)
{
    const int idx = blockIdx.x * blockDim.x + threadIdx.x;   // 16384
    const int d = idx & (DI - 1);
    const int b = idx >> 10;
    const float w0 = w[d * 4 + 0], w1 = w[d * 4 + 1];
    const float w2 = w[d * 4 + 2], w3 = w[d * 4 + 3];
    const float bias = cb[d];
    const float* xp = xz + (size_t)b * L_ * (2 * DI) + d;
    float*       yp = xi + (size_t)b * L_ * DI + d;
    float x0 = 0.f, x1 = 0.f, x2 = 0.f;
    for (int t = 0; t < L_; t++) {
        const float x3 = xp[(size_t)t * (2 * DI)];
        float v = fmaf(w0, x0, fmaf(w1, x1, fmaf(w2, x2, fmaf(w3, x3, bias))));
        yp[(size_t)t * DI] = v / (1.0f + expf(-v));
        x0 = x1; x1 = x2; x2 = x3;
    }
}

// ===========================================================================
// Selective scan: one thread per (b, d), 2 states, L=256 steps.
// Fused: recurrence + C-projection + D skip + silu(z) gate.
// ===========================================================================
__global__ void scan_kernel(const float* __restrict__ dt,
                            const float* __restrict__ xi,
                            const float* __restrict__ dbl,
                            const float* __restrict__ xz,
                            const float* __restrict__ Alog,
                            const float* __restrict__ Dp,
                            float* __restrict__ y)
{
    const int idx = blockIdx.x * blockDim.x + threadIdx.x;
    const int d = idx & (DI - 1);
    const int b = idx >> 10;
    const float A0 = -expf(Alog[d * 2 + 0]);
    const float A1 = -expf(Alog[d * 2 + 1]);
    const float Dd = Dp[d];
    const size_t rbase = (size_t)b * L_;
    float h0 = 0.f, h1 = 0.f;
    for (int t = 0; t < L_; t++) {
        const size_t r = rbase + t;
        const float dtv = dt[r * DI + d];
        const float xv  = xi[r * DI + d];
        const float zv  = xz[r * (2 * DI) + DI + d];
        const float* q  = dbl + r * DBLW + DTR;
        const float B0 = q[0], B1 = q[1], C0 = q[2], C1 = q[3];
        const float dx = dtv * xv;
        h0 = fmaf(expf(dtv * A0), h0, dx * B0);
        h1 = fmaf(expf(dtv * A1), h1, dx * B1);
        float yv = fmaf(h0, C0, fmaf(h1, C1, Dd * xv));
        yv *= zv / (1.0f + expf(-zv));
        y[r * DI + d] = yv;
    }
}

// ===========================================================================
// LayerNorm over last dim (1024), one block per row, eps = 1e-5.
// ===========================================================================
__global__ void ln_kernel(const float* __restrict__ in,
                          const float* __restrict__ g,
                          const float* __restrict__ bt,
                          float* __restrict__ out)
{
    const int row = blockIdx.x;
    const float* x = in  + (size_t)row * DM;
    float*       o = out + (size_t)row * DM;
    float v[4];
    float s = 0.f, s2 = 0.f;
#pragma unroll
    for (int i = 0; i < 4; i++) {
        v[i] = x[threadIdx.x + i * 256];
        s += v[i]; s2 += v[i] * v[i];
    }
#pragma unroll
    for (int off = 16; off > 0; off >>= 1) {
        s  += __shfl_down_sync(0xFFFFFFFFu, s,  off);
        s2 += __shfl_down_sync(0xFFFFFFFFu, s2, off);
    }
    __shared__ float rs[8], rs2[8];
    const int wid = threadIdx.x >> 5;
    if ((threadIdx.x & 31) == 0) { rs[wid] = s; rs2[wid] = s2; }
    __syncthreads();
    float ts = 0.f, ts2 = 0.f;
#pragma unroll
    for (int i = 0; i < 8; i++) { ts += rs[i]; ts2 += rs2[i]; }
    const float mean = ts * (1.0f / DM);
    const float var  = ts2 * (1.0f / DM) - mean * mean;
    const float inv  = rsqrtf(var + 1e-5f);
#pragma unroll
    for (int i = 0; i < 4; i++) {
        const int c = threadIdx.x + i * 256;
        o[c] = (v[i] - mean) * inv * g[c] + bt[c];
    }
}

// ===========================================================================
// out = silu(a + b)
// ===========================================================================
__global__ void add_silu_kernel(const float* __restrict__ a,
                                const float* __restrict__ b,
                                float* __restrict__ o, int n)
{
    const int i = blockIdx.x * blockDim.x + threadIdx.x;
    if (i < n) {
        const float v = a[i] + b[i];
        o[i] = v / (1.0f + expf(-v));
    }
}

// ===========================================================================
// Host orchestration
// ===========================================================================
static void run_mamba(const float* x_in,
                      const float* Win, const float* convw, const float* convb,
                      const float* Wx, const float* Wdt, const float* bdt,
                      const float* Alog, const float* Dp, const float* Wout,
                      float* out,
                      float* xz, float* xi, float* dbl, float* dt, float* y)
{
    // xz = x @ Win^T    : [4096,2048]
    gemm_nt<EPI_NONE><<<dim3(2048 / 64, BL / 64), 256>>>(
        x_in, Win, nullptr, xz, BL, 2 * DI, DM, DM, DM, 2 * DI);
    // xi = silu(causal depthwise conv(xz[:, :DI]) + convb)
    conv_silu_kernel<<<(B_ * DI) / 256, 256>>>(xz, convw, convb, xi);
    // dbl = xi @ Wx^T   : [4096,68]
    gemm_nt<EPI_NONE><<<dim3(2, BL / 64), 256>>>(
        xi, Wx, nullptr, dbl, BL, DBLW, DI, DI, DI, DBLW);
    // dt = softplus(dbl[:, :64] @ Wdt^T + bdt) : [4096,1024]
    gemm_nt<EPI_BIAS_SOFTPLUS><<<dim3(DI / 64, BL / 64), 256>>>(
        dbl, Wdt, bdt, dt, BL, DI, DTR, DBLW, DTR, DI);
    // y = scan + gate
    scan_kernel<<<(B_ * DI) / 128, 128>>>(dt, xi, dbl, xz, Alog, Dp, y);
    // out = y @ Wout^T  : [4096,1024]
    gemm_nt<EPI_NONE><<<dim3(DI / 64, BL / 64), 256>>>(
        y, Wout, nullptr, out, BL, DM, DI, DI, DI, DM);
}

extern "C" void kernel_launch(void* const* d_in, const int* in_sizes, int n_in,
                              void* d_out, int out_size)
{
    const float* x        = (const float*)d_in[0];
    const float* m1_Win   = (const float*)d_in[1];
    const float* m1_convw = (const float*)d_in[2];
    const float* m1_convb = (const float*)d_in[3];
    const float* m1_Wx    = (const float*)d_in[4];
    const float* m1_Wdt   = (const float*)d_in[5];
    const float* m1_bdt   = (const float*)d_in[6];
    const float* m1_Alog  = (const float*)d_in[7];
    const float* m1_D     = (const float*)d_in[8];
    const float* m1_Wout  = (const float*)d_in[9];
    const float* m2_Win   = (const float*)d_in[10];
    const float* m2_convw = (const float*)d_in[11];
    const float* m2_convb = (const float*)d_in[12];
    const float* m2_Wx    = (const float*)d_in[13];
    const float* m2_Wdt   = (const float*)d_in[14];
    const float* m2_bdt   = (const float*)d_in[15];
    const float* m2_Alog  = (const float*)d_in[16];
    const float* m2_D     = (const float*)d_in[17];
    const float* m2_Wout  = (const float*)d_in[18];
    const float* ln1_g    = (const float*)d_in[19];
    const float* ln1_b    = (const float*)d_in[20];
    const float* ln2_g    = (const float*)d_in[21];
    const float* ln2_b    = (const float*)d_in[22];
    const float* W_mid    = (const float*)d_in[23];
    const float* W_spa    = (const float*)d_in[24];
    const float* b_spa    = (const float*)d_in[25];
    const float* W_res    = (const float*)d_in[26];

    float *xz, *xi, *dbl, *dt, *y, *bufA, *bufB, *bufC;
    cudaGetSymbolAddress((void**)&xz,   g_xz);
    cudaGetSymbolAddress((void**)&xi,   g_xi);
    cudaGetSymbolAddress((void**)&dbl,  g_dbl);
    cudaGetSymbolAddress((void**)&dt,   g_dt);
    cudaGetSymbolAddress((void**)&y,    g_y);
    cudaGetSymbolAddress((void**)&bufA, g_bufA);
    cudaGetSymbolAddress((void**)&bufB, g_bufB);
    cudaGetSymbolAddress((void**)&bufC, g_bufC);

    // s = mamba1(x)
    run_mamba(x, m1_Win, m1_convw, m1_convb, m1_Wx, m1_Wdt, m1_bdt,
              m1_Alog, m1_D, m1_Wout, bufA, xz, xi, dbl, dt, y);
    // s = ln1(s)
    ln_kernel<<<BL, 256>>>(bufA, ln1_g, ln1_b, bufA);
    // s = silu(W_mid channel mix)
    gemm_nn_batched<EPI_SILU><<<dim3(DM / 64, 256 / 64, B_), 256>>>(
        W_mid, bufA, bufB, 256, DM, 256, (long)256 * DM, (long)256 * DM);
    // s = mamba2(s)
    run_mamba(bufB, m2_Win, m2_convw, m2_convb, m2_Wx, m2_Wdt, m2_bdt,
              m2_Alog, m2_D, m2_Wout, bufA, xz, xi, dbl, dt, y);
    // s = ln2(s)
    ln_kernel<<<BL, 256>>>(bufA, ln2_g, ln2_b, bufA);
    // r = silu(x @ W_spa^T + b_spa)
    gemm_nt<EPI_BIAS_SILU><<<dim3(DM / 64, BL / 64), 256>>>(
        x, W_spa, b_spa, bufC, BL, DM, DM, DM, DM, DM);
    // r = silu(W_res channel mix)
    gemm_nn_batched<EPI_SILU><<<dim3(DM / 64, 256 / 64, B_), 256>>>(
        W_res, bufC, bufB, 256, DM, 256, (long)256 * DM, (long)256 * DM);
    // out = silu(s + r)
    add_silu_kernel<<<(BL * DM) / 256, 256>>>(bufA, bufB, (float*)d_out, BL * DM);
}

// round 3
// speedup vs baseline: 2.5617x; 2.5617x over previous
#include <cuda_runtime.h>
#include <cuda_bf16.h>
#include <math.h>

// Problem dims (fixed by the dataset)
#define B_    16
#define L_    256
#define DM    1024
#define DI    1024
#define DTR   64
#define BL    (B_ * L_)      // 4096 rows
#define DBLW  68             // dtr + 2*n = 64 + 4

// ---------------- scratch (static device globals; no allocation allowed) ---
__device__ float g_xz [BL * 2 * DI];
__device__ float g_xi [BL * DI];
__device__ float g_dbl[BL * DBLW];
__device__ float g_dt [BL * DI];
__device__ float g_y  [BL * DI];
__device__ float g_bufA[BL * DM];
__device__ float g_bufB[BL * DM];
__device__ float g_bufC[BL * DM];

// ---------------- epilogue modes ------------------------------------------
#define EPI_NONE          0
#define EPI_SILU          1
#define EPI_BIAS_SILU     2
#define EPI_BIAS_SOFTPLUS 3

template <int EPI>
__device__ __forceinline__ float epi_apply(float v, float bia) {
    if (EPI == EPI_BIAS_SILU || EPI == EPI_BIAS_SOFTPLUS) v += bia;
    if (EPI == EPI_SILU || EPI == EPI_BIAS_SILU) v = v / (1.0f + expf(-v));
    if (EPI == EPI_BIAS_SOFTPLUS) v = (v > 20.0f) ? v : log1pf(expf(v));
    return v;
}

// ===========================================================================
// Tensor-core NT GEMM with 3-term bf16 split (fp32-grade accuracy).
// C[M,N] = epi( A[M,K] @ B[N,K]^T + bias[n] )
// Requirements (all call sites satisfy): M%128==0, N%128==0, K%32==0,
// lda/ldb multiples of 4 (16B-aligned rows).
// Tiles: 128x128x32, 256 threads (8 warps as 2x4; warp tile 64x32).
// smem: double-buffered, per stage {A_hi,A_lo,B_hi,B_lo} bf16 with 64B rows
// + SW64 swizzle for conflict-free ldmatrix. 64 KB dynamic smem.
// ===========================================================================

#define LDSM4(r0, r1, r2, r3, addr)                                            \
    asm volatile("ldmatrix.sync.aligned.m8n8.x4.shared.b16 {%0,%1,%2,%3}, [%4];" \
                 : "=r"(r0), "=r"(r1), "=r"(r2), "=r"(r3) : "r"(addr))

#define MMA16816(d, a, b)                                                      \
    asm volatile("mma.sync.aligned.m16n8k16.row.col.f32.bf16.bf16.f32 "        \
                 "{%0,%1,%2,%3},{%4,%5,%6,%7},{%8,%9},{%0,%1,%2,%3};"          \
                 : "+f"(d[0]), "+f"(d[1]), "+f"(d[2]), "+f"(d[3])              \
                 : "r"(a[0]), "r"(a[1]), "r"(a[2]), "r"(a[3]),                 \
                   "r"(b[0]), "r"(b[1]))

// split 8 floats into packed bf16 hi/lo pairs (4 u32 each)
__device__ __forceinline__ void cvt_split8(const float* v, unsigned* hi, unsigned* lo) {
#pragma unroll
    for (int i = 0; i < 4; i++) {
        const float a = v[2 * i], b = v[2 * i + 1];
        __nv_bfloat16 ha = __float2bfloat16_rn(a);
        __nv_bfloat16 hb = __float2bfloat16_rn(b);
        const float la = a - __bfloat162float(ha);
        const float lb = b - __bfloat162float(hb);
        __nv_bfloat162 hp; hp.x = ha; hp.y = hb;
        __nv_bfloat162 lp; lp.x = __float2bfloat16_rn(la); lp.y = __float2bfloat16_rn(lb);
        hi[i] = *(const unsigned*)&hp;
        lo[i] = *(const unsigned*)&lp;
    }
}

// stage layout (bytes): A_hi @0, A_lo @8192, B_hi @16384, B_lo @24576; stage size 32768
#define STG_SZ   32768
#define A_LO_OFF 8192
#define B_HI_OFF 16384
#define B_LO_OFF 24576

__device__ __forceinline__ void cvt_store_stage(const float* ra, const float* rb,
                                                char* st, int stoff0, int stoff1) {
    unsigned h[4], l[4];
    cvt_split8(ra, h, l);
    *(uint4*)(st + stoff0)            = make_uint4(h[0], h[1], h[2], h[3]);
    *(uint4*)(st + A_LO_OFF + stoff0) = make_uint4(l[0], l[1], l[2], l[3]);
    cvt_split8(ra + 8, h, l);
    *(uint4*)(st + stoff1)            = make_uint4(h[0], h[1], h[2], h[3]);
    *(uint4*)(st + A_LO_OFF + stoff1) = make_uint4(l[0], l[1], l[2], l[3]);
    cvt_split8(rb, h, l);
    *(uint4*)(st + B_HI_OFF + stoff0) = make_uint4(h[0], h[1], h[2], h[3]);
    *(uint4*)(st + B_LO_OFF + stoff0) = make_uint4(l[0], l[1], l[2], l[3]);
    cvt_split8(rb + 8, h, l);
    *(uint4*)(st + B_HI_OFF + stoff1) = make_uint4(h[0], h[1], h[2], h[3]);
    *(uint4*)(st + B_LO_OFF + stoff1) = make_uint4(l[0], l[1], l[2], l[3]);
}

template <int EPI>
__global__ void __launch_bounds__(256) gemm_nt_mma(
    const float* __restrict__ A, const float* __restrict__ B,
    const float* __restrict__ bias, float* __restrict__ C,
    int M, int N, int K, int lda, int ldb, int ldc)
{
    extern __shared__ char sm[];
    const int tid  = threadIdx.x;
    const int lane = tid & 31;
    const int warp = tid >> 5;
    const int wm   = warp >> 2;        // 0..1 -> 64 rows each
    const int wn   = warp & 3;         // 0..3 -> 32 cols each
    const int bm   = blockIdx.y * 128;
    const int bn   = blockIdx.x * 128;

    float acc[4][4][4];
#pragma unroll
    for (int i = 0; i < 4; i++)
#pragma unroll
        for (int j = 0; j < 4; j++)
#pragma unroll
            for (int c = 0; c < 4; c++) acc[i][j][c] = 0.0f;

    // global prefetch mapping: thread t -> row t>>1 (0..127), 16 k-floats at (t&1)*16
    const int prow = tid >> 1;
    const int pkh  = (tid & 1) << 4;
    const float* pA = A + (size_t)(bm + prow) * lda + pkh;
    const float* pB = B + (size_t)(bn + prow) * ldb + pkh;

    // swizzled STS offsets (64B rows, SW64: flip byte-bits[5:4] by row-bits[2:1])
    const int swm    = ((prow >> 1) & 3) << 4;
    const int rowb   = prow * 64;
    const int kb0    = (tid & 1) << 5;
    const int stoff0 = rowb + ((kb0 +  0) ^ swm);
    const int stoff1 = rowb + ((kb0 + 16) ^ swm);

    const unsigned smu = (unsigned)__cvta_generic_to_shared(sm);

    float ra[16], rb[16];
#pragma unroll
    for (int i = 0; i < 4; i++) {
        *(float4*)(ra + 4 * i) = *(const float4*)(pA + 4 * i);
        *(float4*)(rb + 4 * i) = *(const float4*)(pB + 4 * i);
    }
    cvt_store_stage(ra, rb, sm, stoff0, stoff1);
    __syncthreads();

    const int nstage = K >> 5;
    int buf = 0;

    for (int s = 1; s <= nstage; s++) {
        const bool more = (s < nstage);
        if (more) {
            const int k0 = s << 5;
#pragma unroll
            for (int i = 0; i < 4; i++) {
                *(float4*)(ra + 4 * i) = *(const float4*)(pA + k0 + 4 * i);
                *(float4*)(rb + 4 * i) = *(const float4*)(pB + k0 + 4 * i);
            }
        }

        const unsigned stage = smu + buf * STG_SZ;
#pragma unroll
        for (int kk = 0; kk < 2; kk++) {
            unsigned Ahi[4][4], Alo[4][4];
#pragma unroll
            for (int mt = 0; mt < 4; mt++) {
                const int row = wm * 64 + mt * 16 + (lane & 15);
                const int kb  = kk * 32 + ((lane >> 4) << 4);
                const int off = row * 64 + (kb ^ (((row >> 1) & 3) << 4));
                LDSM4(Ahi[mt][0], Ahi[mt][1], Ahi[mt][2], Ahi[mt][3], stage + off);
                LDSM4(Alo[mt][0], Alo[mt][1], Alo[mt][2], Alo[mt][3], stage + A_LO_OFF + off);
            }
            unsigned Bhi[4][2], Blo[4][2];
#pragma unroll
            for (int np = 0; np < 2; np++) {
                const int row = wn * 32 + np * 16 + (lane & 7) + ((lane >> 4) << 3);
                const int kb  = kk * 32 + (((lane >> 3) & 1) << 4);
                const int off = row * 64 + (kb ^ (((row >> 1) & 3) << 4));
                unsigned r0, r1, r2, r3;
                LDSM4(r0, r1, r2, r3, stage + B_HI_OFF + off);
                Bhi[np * 2][0] = r0; Bhi[np * 2][1] = r1;
                Bhi[np * 2 + 1][0] = r2; Bhi[np * 2 + 1][1] = r3;
                LDSM4(r0, r1, r2, r3, stage + B_LO_OFF + off);
                Blo[np * 2][0] = r0; Blo[np * 2][1] = r1;
                Blo[np * 2 + 1][0] = r2; Blo[np * 2 + 1][1] = r3;
            }
#pragma unroll
            for (int mt = 0; mt < 4; mt++) {
#pragma unroll
                for (int nt = 0; nt < 4; nt++) {
                    MMA16816(acc[mt][nt], Ahi[mt], Bhi[nt]);
                    MMA16816(acc[mt][nt], Ahi[mt], Blo[nt]);
                    MMA16816(acc[mt][nt], Alo[mt], Bhi[nt]);
                }
            }
        }

        if (more) {
            cvt_store_stage(ra, rb, sm + (buf ^ 1) * STG_SZ, stoff0, stoff1);
            __syncthreads();
            buf ^= 1;
        }
    }

    // epilogue
#pragma unroll
    for (int mt = 0; mt < 4; mt++) {
#pragma unroll
        for (int nt = 0; nt < 4; nt++) {
            const int row0 = bm + wm * 64 + mt * 16 + (lane >> 2);
            const int col0 = bn + wn * 32 + nt * 8 + ((lane & 3) << 1);
            float b0 = 0.f, b1 = 0.f;
            if (EPI == EPI_BIAS_SILU || EPI == EPI_BIAS_SOFTPLUS) {
                b0 = bias[col0]; b1 = bias[col0 + 1];
            }
            float2 v;
            v.x = epi_apply<EPI>(acc[mt][nt][0], b0);
            v.y = epi_apply<EPI>(acc[mt][nt][1], b1);
            *(float2*)(C + (size_t)row0 * ldc + col0) = v;
            v.x = epi_apply<EPI>(acc[mt][nt][2], b0);
            v.y = epi_apply<EPI>(acc[mt][nt][3], b1);
            *(float2*)(C + (size_t)(row0 + 8) * ldc + col0) = v;
        }
    }
}

// ===========================================================================
// SIMT NT GEMM (kept for small/odd shapes: Wx with N=68)
// ===========================================================================
template <int EPI>
__global__ void __launch_bounds__(256) gemm_nt(
    const float* __restrict__ A, const float* __restrict__ B,
    const float* __restrict__ bias, float* __restrict__ C,
    int M, int N, int K, int lda, int ldb, int ldc)
{
    __shared__ float As[16][68];
    __shared__ float Bs[16][68];

    const int tid = threadIdx.x;
    const int tx  = tid & 15;
    const int ty  = tid >> 4;
    const int bm  = blockIdx.y * 64;
    const int bn  = blockIdx.x * 64;
    const int lrow = tid >> 2;
    const int lcol = (tid & 3) << 2;

    float acc[4][4];
#pragma unroll
    for (int i = 0; i < 4; i++)
#pragma unroll
        for (int j = 0; j < 4; j++) acc[i][j] = 0.0f;

    for (int k0 = 0; k0 < K; k0 += 16) {
        float4 av = make_float4(0.f, 0.f, 0.f, 0.f);
        float4 bv = make_float4(0.f, 0.f, 0.f, 0.f);
        const int am = bm + lrow;
        if (am < M) av = *(const float4*)(A + (size_t)am * lda + k0 + lcol);
        const int bnr = bn + lrow;
        if (bnr < N) bv = *(const float4*)(B + (size_t)bnr * ldb + k0 + lcol);

        As[lcol + 0][lrow] = av.x; As[lcol + 1][lrow] = av.y;
        As[lcol + 2][lrow] = av.z; As[lcol + 3][lrow] = av.w;
        Bs[lcol + 0][lrow] = bv.x; Bs[lcol + 1][lrow] = bv.y;
        Bs[lcol + 2][lrow] = bv.z; Bs[lcol + 3][lrow] = bv.w;
        __syncthreads();

#pragma unroll
        for (int k = 0; k < 16; k++) {
            const float4 raf = *(const float4*)&As[k][ty << 2];
            const float4 rbf = *(const float4*)&Bs[k][tx << 2];
            const float a0 = raf.x, a1 = raf.y, a2 = raf.z, a3 = raf.w;
            const float b0 = rbf.x, b1 = rbf.y, b2 = rbf.z, b3 = rbf.w;
            acc[0][0] = fmaf(a0, b0, acc[0][0]); acc[0][1] = fmaf(a0, b1, acc[0][1]);
            acc[0][2] = fmaf(a0, b2, acc[0][2]); acc[0][3] = fmaf(a0, b3, acc[0][3]);
            acc[1][0] = fmaf(a1, b0, acc[1][0]); acc[1][1] = fmaf(a1, b1, acc[1][1]);
            acc[1][2] = fmaf(a1, b2, acc[1][2]); acc[1][3] = fmaf(a1, b3, acc[1][3]);
            acc[2][0] = fmaf(a2, b0, acc[2][0]); acc[2][1] = fmaf(a2, b1, acc[2][1]);
            acc[2][2] = fmaf(a2, b2, acc[2][2]); acc[2][3] = fmaf(a2, b3, acc[2][3]);
            acc[3][0] = fmaf(a3, b0, acc[3][0]); acc[3][1] = fmaf(a3, b1, acc[3][1]);
            acc[3][2] = fmaf(a3, b2, acc[3][2]); acc[3][3] = fmaf(a3, b3, acc[3][3]);
        }
        __syncthreads();
    }

#pragma unroll
    for (int i = 0; i < 4; i++) {
        const int m = bm + (ty << 2) + i;
        if (m >= M) continue;
#pragma unroll
        for (int j = 0; j < 4; j++) {
            const int n = bn + (tx << 2) + j;
            if (n >= N) continue;
            float bia = (EPI == EPI_BIAS_SILU || EPI == EPI_BIAS_SOFTPLUS) ? bias[n] : 0.f;
            C[(size_t)m * ldc + n] = epi_apply<EPI>(acc[i][j], bia);
        }
    }
}

// ===========================================================================
// Batched NN GEMM (channel mix): C[z][o,s] = epi( sum_c W[o,c] * X[z][c,s] )
// ===========================================================================
template <int EPI>
__global__ void __launch_bounds__(256) gemm_nn_batched(
    const float* __restrict__ W, const float* __restrict__ X,
    float* __restrict__ C,
    int M, int N, int K, long strideX, long strideC)
{
    const float* Xb = X + (size_t)blockIdx.z * strideX;
    float*       Cb = C + (size_t)blockIdx.z * strideC;

    __shared__ float As[16][68];
    __shared__ float Bs[16][68];

    const int tid = threadIdx.x;
    const int tx  = tid & 15;
    const int ty  = tid >> 4;
    const int bm  = blockIdx.y * 64;
    const int bn  = blockIdx.x * 64;
    const int lrow = tid >> 2;
    const int lcol = (tid & 3) << 2;
    const int xk  = tid >> 4;
    const int xn  = (tid & 15) << 2;

    float acc[4][4];
#pragma unroll
    for (int i = 0; i < 4; i++)
#pragma unroll
        for (int j = 0; j < 4; j++) acc[i][j] = 0.0f;

    for (int k0 = 0; k0 < K; k0 += 16) {
        float4 av = make_float4(0.f, 0.f, 0.f, 0.f);
        const int am = bm + lrow;
        if (am < M) av = *(const float4*)(W + (size_t)am * K + k0 + lcol);
        As[lcol + 0][lrow] = av.x; As[lcol + 1][lrow] = av.y;
        As[lcol + 2][lrow] = av.z; As[lcol + 3][lrow] = av.w;

        float4 xv = make_float4(0.f, 0.f, 0.f, 0.f);
        const int gn = bn + xn;
        if (gn < N) xv = *(const float4*)(Xb + (size_t)(k0 + xk) * N + gn);
        *(float4*)&Bs[xk][xn] = xv;
        __syncthreads();

#pragma unroll
        for (int k = 0; k < 16; k++) {
            const float4 raf = *(const float4*)&As[k][ty << 2];
            const float4 rbf = *(const float4*)&Bs[k][tx << 2];
            const float a0 = raf.x, a1 = raf.y, a2 = raf.z, a3 = raf.w;
            const float b0 = rbf.x, b1 = rbf.y, b2 = rbf.z, b3 = rbf.w;
            acc[0][0] = fmaf(a0, b0, acc[0][0]); acc[0][1] = fmaf(a0, b1, acc[0][1]);
            acc[0][2] = fmaf(a0, b2, acc[0][2]); acc[0][3] = fmaf(a0, b3, acc[0][3]);
            acc[1][0] = fmaf(a1, b0, acc[1][0]); acc[1][1] = fmaf(a1, b1, acc[1][1]);
            acc[1][2] = fmaf(a1, b2, acc[1][2]); acc[1][3] = fmaf(a1, b3, acc[1][3]);
            acc[2][0] = fmaf(a2, b0, acc[2][0]); acc[2][1] = fmaf(a2, b1, acc[2][1]);
            acc[2][2] = fmaf(a2, b2, acc[2][2]); acc[2][3] = fmaf(a2, b3, acc[2][3]);
            acc[3][0] = fmaf(a3, b0, acc[3][0]); acc[3][1] = fmaf(a3, b1, acc[3][1]);
            acc[3][2] = fmaf(a3, b2, acc[3][2]); acc[3][3] = fmaf(a3, b3, acc[3][3]);
        }
        __syncthreads();
    }

#pragma unroll
    for (int i = 0; i < 4; i++) {
        const int m = bm + (ty << 2) + i;
        if (m >= M) continue;
#pragma unroll
        for (int j = 0; j < 4; j++) {
            const int n = bn + (tx << 2) + j;
            if (n >= N) continue;
            Cb[(size_t)m * N + n] = epi_apply<EPI>(acc[i][j], 0.f);
        }
    }
}

// ===========================================================================
// Depthwise causal conv (k=4) along L + bias + silu.
// ===========================================================================
__global__ void conv_silu_kernel(const float* __restrict__ xz,
                                 const float* __restrict__ w,
                                 const float* __restrict__ cb,
                                 float* __restrict__ xi)
{
    const int idx = blockIdx.x * blockDim.x + threadIdx.x;
    const int d = idx & (DI - 1);
    const int b = idx >> 10;
    const float w0 = w[d * 4 + 0], w1 = w[d * 4 + 1];
    const float w2 = w[d * 4 + 2], w3 = w[d * 4 + 3];
    const float bias = cb[d];
    const float* xp = xz + (size_t)b * L_ * (2 * DI) + d;
    float*       yp = xi + (size_t)b * L_ * DI + d;
    float x0 = 0.f, x1 = 0.f, x2 = 0.f;
    for (int t = 0; t < L_; t++) {
        const float x3 = xp[(size_t)t * (2 * DI)];
        float v = fmaf(w0, x0, fmaf(w1, x1, fmaf(w2, x2, fmaf(w3, x3, bias))));
        yp[(size_t)t * DI] = v / (1.0f + expf(-v));
        x0 = x1; x1 = x2; x2 = x3;
    }
}

// ===========================================================================
// Selective scan: one thread per (b, d), 2 states, L=256 steps.
// ===========================================================================
__global__ void scan_kernel(const float* __restrict__ dt,
                            const float* __restrict__ xi,
                            const float* __restrict__ dbl,
                            const float* __restrict__ xz,
                            const float* __restrict__ Alog,
                            const float* __restrict__ Dp,
                            float* __restrict__ y)
{
    const int idx = blockIdx.x * blockDim.x + threadIdx.x;
    const int d = idx & (DI - 1);
    const int b = idx >> 10;
    const float A0 = -expf(Alog[d * 2 + 0]);
    const float A1 = -expf(Alog[d * 2 + 1]);
    const float Dd = Dp[d];
    const size_t rbase = (size_t)b * L_;
    float h0 = 0.f, h1 = 0.f;
    for (int t = 0; t < L_; t++) {
        const size_t r = rbase + t;
        const float dtv = dt[r * DI + d];
        const float xv  = xi[r * DI + d];
        const float zv  = xz[r * (2 * DI) + DI + d];
        const float* q  = dbl + r * DBLW + DTR;
        const float B0 = q[0], B1 = q[1], C0 = q[2], C1 = q[3];
        const float dx = dtv * xv;
        h0 = fmaf(expf(dtv * A0), h0, dx * B0);
        h1 = fmaf(expf(dtv * A1), h1, dx * B1);
        float yv = fmaf(h0, C0, fmaf(h1, C1, Dd * xv));
        yv *= zv / (1.0f + expf(-zv));
        y[r * DI + d] = yv;
    }
}

// ===========================================================================
// LayerNorm over last dim (1024), one block per row, eps = 1e-5.
// ===========================================================================
__global__ void ln_kernel(const float* __restrict__ in,
                          const float* __restrict__ g,
                          const float* __restrict__ bt,
                          float* __restrict__ out)
{
    const int row = blockIdx.x;
    const float* x = in  + (size_t)row * DM;
    float*       o = out + (size_t)row * DM;
    float v[4];
    float s = 0.f, s2 = 0.f;
#pragma unroll
    for (int i = 0; i < 4; i++) {
        v[i] = x[threadIdx.x + i * 256];
        s += v[i]; s2 += v[i] * v[i];
    }
#pragma unroll
    for (int off = 16; off > 0; off >>= 1) {
        s  += __shfl_down_sync(0xFFFFFFFFu, s,  off);
        s2 += __shfl_down_sync(0xFFFFFFFFu, s2, off);
    }
    __shared__ float rs[8], rs2[8];
    const int wid = threadIdx.x >> 5;
    if ((threadIdx.x & 31) == 0) { rs[wid] = s; rs2[wid] = s2; }
    __syncthreads();
    float ts = 0.f, ts2 = 0.f;
#pragma unroll
    for (int i = 0; i < 8; i++) { ts += rs[i]; ts2 += rs2[i]; }
    const float mean = ts * (1.0f / DM);
    const float var  = ts2 * (1.0f / DM) - mean * mean;
    const float inv  = rsqrtf(var + 1e-5f);
#pragma unroll
    for (int i = 0; i < 4; i++) {
        const int c = threadIdx.x + i * 256;
        o[c] = (v[i] - mean) * inv * g[c] + bt[c];
    }
}

__global__ void add_silu_kernel(const float* __restrict__ a,
                                const float* __restrict__ b,
                                float* __restrict__ o, int n)
{
    const int i = blockIdx.x * blockDim.x + threadIdx.x;
    if (i < n) {
        const float v = a[i] + b[i];
        o[i] = v / (1.0f + expf(-v));
    }
}

// ===========================================================================
// Host orchestration
// ===========================================================================
#define MMA_SMEM 65536

static void run_mamba(const float* x_in,
                      const float* Win, const float* convw, const float* convb,
                      const float* Wx, const float* Wdt, const float* bdt,
                      const float* Alog, const float* Dp, const float* Wout,
                      float* out,
                      float* xz, float* xi, float* dbl, float* dt, float* y)
{
    // xz = x @ Win^T : [4096, 2048]
    gemm_nt_mma<EPI_NONE><<<dim3(2048 / 128, BL / 128), 256, MMA_SMEM>>>(
        x_in, Win, nullptr, xz, BL, 2 * DI, DM, DM, DM, 2 * DI);
    // xi = silu(causal depthwise conv(xz[:, :DI]) + convb)
    conv_silu_kernel<<<(B_ * DI) / 256, 256>>>(xz, convw, convb, xi);
    // dbl = xi @ Wx^T : [4096, 68]  (N=68 -> SIMT)
    gemm_nt<EPI_NONE><<<dim3(2, BL / 64), 256>>>(
        xi, Wx, nullptr, dbl, BL, DBLW, DI, DI, DI, DBLW);
    // dt = softplus(dbl[:, :64] @ Wdt^T + bdt) : [4096, 1024]
    gemm_nt_mma<EPI_BIAS_SOFTPLUS><<<dim3(DI / 128, BL / 128), 256, MMA_SMEM>>>(
        dbl, Wdt, bdt, dt, BL, DI, DTR, DBLW, DTR, DI);
    // y = scan + gate
    scan_kernel<<<(B_ * DI) / 128, 128>>>(dt, xi, dbl, xz, Alog, Dp, y);
    // out = y @ Wout^T : [4096, 1024]
    gemm_nt_mma<EPI_NONE><<<dim3(DM / 128, BL / 128), 256, MMA_SMEM>>>(
        y, Wout, nullptr, out, BL, DM, DI, DI, DI, DM);
}

extern "C" void kernel_launch(void* const* d_in, const int* in_sizes, int n_in,
                              void* d_out, int out_size)
{
    const float* x        = (const float*)d_in[0];
    const float* m1_Win   = (const float*)d_in[1];
    const float* m1_convw = (const float*)d_in[2];
    const float* m1_convb = (const float*)d_in[3];
    const float* m1_Wx    = (const float*)d_in[4];
    const float* m1_Wdt   = (const float*)d_in[5];
    const float* m1_bdt   = (const float*)d_in[6];
    const float* m1_Alog  = (const float*)d_in[7];
    const float* m1_D     = (const float*)d_in[8];
    const float* m1_Wout  = (const float*)d_in[9];
    const float* m2_Win   = (const float*)d_in[10];
    const float* m2_convw = (const float*)d_in[11];
    const float* m2_convb = (const float*)d_in[12];
    const float* m2_Wx    = (const float*)d_in[13];
    const float* m2_Wdt   = (const float*)d_in[14];
    const float* m2_bdt   = (const float*)d_in[15];
    const float* m2_Alog  = (const float*)d_in[16];
    const float* m2_D     = (const float*)d_in[17];
    const float* m2_Wout  = (const float*)d_in[18];
    const float* ln1_g    = (const float*)d_in[19];
    const float* ln1_b    = (const float*)d_in[20];
    const float* ln2_g    = (const float*)d_in[21];
    const float* ln2_b    = (const float*)d_in[22];
    const float* W_mid    = (const float*)d_in[23];
    const float* W_spa    = (const float*)d_in[24];
    const float* b_spa    = (const float*)d_in[25];
    const float* W_res    = (const float*)d_in[26];

    cudaFuncSetAttribute(gemm_nt_mma<EPI_NONE>,
                         cudaFuncAttributeMaxDynamicSharedMemorySize, MMA_SMEM);
    cudaFuncSetAttribute(gemm_nt_mma<EPI_BIAS_SILU>,
                         cudaFuncAttributeMaxDynamicSharedMemorySize, MMA_SMEM);
    cudaFuncSetAttribute(gemm_nt_mma<EPI_BIAS_SOFTPLUS>,
                         cudaFuncAttributeMaxDynamicSharedMemorySize, MMA_SMEM);

    float *xz, *xi, *dbl, *dt, *y, *bufA, *bufB, *bufC;
    cudaGetSymbolAddress((void**)&xz,   g_xz);
    cudaGetSymbolAddress((void**)&xi,   g_xi);
    cudaGetSymbolAddress((void**)&dbl,  g_dbl);
    cudaGetSymbolAddress((void**)&dt,   g_dt);
    cudaGetSymbolAddress((void**)&y,    g_y);
    cudaGetSymbolAddress((void**)&bufA, g_bufA);
    cudaGetSymbolAddress((void**)&bufB, g_bufB);
    cudaGetSymbolAddress((void**)&bufC, g_bufC);

    // s = mamba1(x)
    run_mamba(x, m1_Win, m1_convw, m1_convb, m1_Wx, m1_Wdt, m1_bdt,
              m1_Alog, m1_D, m1_Wout, bufA, xz, xi, dbl, dt, y);
    // s = ln1(s)
    ln_kernel<<<BL, 256>>>(bufA, ln1_g, ln1_b, bufA);
    // s = silu(W_mid channel mix)
    gemm_nn_batched<EPI_SILU><<<dim3(DM / 64, 256 / 64, B_), 256>>>(
        W_mid, bufA, bufB, 256, DM, 256, (long)256 * DM, (long)256 * DM);
    // s = mamba2(s)
    run_mamba(bufB, m2_Win, m2_convw, m2_convb, m2_Wx, m2_Wdt, m2_bdt,
              m2_Alog, m2_D, m2_Wout, bufA, xz, xi, dbl, dt, y);
    // s = ln2(s)
    ln_kernel<<<BL, 256>>>(bufA, ln2_g, ln2_b, bufA);
    // r = silu(x @ W_spa^T + b_spa)
    gemm_nt_mma<EPI_BIAS_SILU><<<dim3(DM / 128, BL / 128), 256, MMA_SMEM>>>(
        x, W_spa, b_spa, bufC, BL, DM, DM, DM, DM, DM);
    // r = silu(W_res channel mix)
    gemm_nn_batched<EPI_SILU><<<dim3(DM / 64, 256 / 64, B_), 256>>>(
        W_res, bufC, bufB, 256, DM, 256, (long)256 * DM, (long)256 * DM);
    // out = silu(s + r)
    add_silu_kernel<<<(BL * DM) / 256, 256>>>(bufA, bufB, (float*)d_out, BL * DM);
}

// round 5
// speedup vs baseline: 2.7075x; 1.0569x over previous
#include <cuda_runtime.h>
#include <cuda_bf16.h>
#include <math.h>

// Problem dims (fixed by the dataset)
#define B_    16
#define L_    256
#define DM    1024
#define DI    1024
#define DTR   64
#define BL    (B_ * L_)      // 4096 rows
#define DBLP  128            // padded dbl width (dtr=64 | B0 B1 C0 C1 | pad)

// ---------------- scratch (static device globals; no allocation allowed) ---
__device__ float g_xz  [BL * 2 * DI];
__device__ float g_xi  [BL * DI];
__device__ float g_dblp[BL * DBLP];
__device__ float g_dt  [BL * DI];
__device__ float g_y   [BL * DI];
__device__ float g_bufA[BL * DM];
__device__ float g_bufB[BL * DM];
__device__ float g_bufC[BL * DM];

// bf16 split buffers
__device__ __nv_bfloat16 g_Xh[BL * DM], g_Xl[BL * DM];     // input x split (persists)
__device__ __nv_bfloat16 g_Ah[BL * DM], g_Al[BL * DM];     // activation scratch
__device__ __nv_bfloat16 g_Wh[2 * DI * DM], g_Wl[2 * DI * DM]; // weight scratch
__device__ __nv_bfloat16 g_Dh[BL * DBLP], g_Dl[BL * DBLP]; // dbl split

// ---------------- epilogue modes ------------------------------------------
#define EPI_NONE          0
#define EPI_SILU          1
#define EPI_BIAS_SILU     2
#define EPI_BIAS_SOFTPLUS 3

template <int EPI>
__device__ __forceinline__ float epi_apply(float v, float bia) {
    if (EPI == EPI_BIAS_SILU || EPI == EPI_BIAS_SOFTPLUS) v += bia;
    if (EPI == EPI_SILU || EPI == EPI_BIAS_SILU) v = v / (1.0f + expf(-v));
    if (EPI == EPI_BIAS_SOFTPLUS) v = (v > 20.0f) ? v : log1pf(expf(v));
    return v;
}

// ===========================================================================
// Split converters: fp32 -> (hi bf16, lo bf16), lo = rn(v - hi)
// ===========================================================================
__device__ __forceinline__ void split1(float v, __nv_bfloat16& h, __nv_bfloat16& l) {
    h = __float2bfloat16_rn(v);
    l = __float2bfloat16_rn(v - __bfloat162float(h));
}

__global__ void split_kernel(const float* __restrict__ in,
                             __nv_bfloat16* __restrict__ hi,
                             __nv_bfloat16* __restrict__ lo, int n4)
{
    const int i = blockIdx.x * blockDim.x + threadIdx.x;
    if (i >= n4) return;
    const float4 v = *(const float4*)(in + 4 * (size_t)i);
    __nv_bfloat16 h0, h1, h2, h3, l0, l1, l2, l3;
    split1(v.x, h0, l0); split1(v.y, h1, l1);
    split1(v.z, h2, l2); split1(v.w, h3, l3);
    __nv_bfloat162 hp0; hp0.x = h0; hp0.y = h1;
    __nv_bfloat162 hp1; hp1.x = h2; hp1.y = h3;
    __nv_bfloat162 lp0; lp0.x = l0; lp0.y = l1;
    __nv_bfloat162 lp1; lp1.x = l2; lp1.y = l3;
    *(uint2*)(hi + 4 * (size_t)i) = make_uint2(*(unsigned*)&hp0, *(unsigned*)&hp1);
    *(uint2*)(lo + 4 * (size_t)i) = make_uint2(*(unsigned*)&lp0, *(unsigned*)&lp1);
}

// pad Wx [68,1024] -> [128,1024] split (rows >= 68 zero)
__global__ void split_pad_wx_kernel(const float* __restrict__ in,
                                    __nv_bfloat16* __restrict__ hi,
                                    __nv_bfloat16* __restrict__ lo)
{
    const int i = blockIdx.x * blockDim.x + threadIdx.x;   // < 32768
    const int i4 = i << 2;
    const int row = i4 >> 10;
    float4 v = make_float4(0.f, 0.f, 0.f, 0.f);
    if (row < 68) v = *(const float4*)(in + (size_t)row * 1024 + (i4 & 1023));
    __nv_bfloat16 h0, h1, h2, h3, l0, l1, l2, l3;
    split1(v.x, h0, l0); split1(v.y, h1, l1);
    split1(v.z, h2, l2); split1(v.w, h3, l3);
    __nv_bfloat162 hp0; hp0.x = h0; hp0.y = h1;
    __nv_bfloat162 hp1; hp1.x = h2; hp1.y = h3;
    __nv_bfloat162 lp0; lp0.x = l0; lp0.y = l1;
    __nv_bfloat162 lp1; lp1.x = l2; lp1.y = l3;
    *(uint2*)(hi + (size_t)i4) = make_uint2(*(unsigned*)&hp0, *(unsigned*)&hp1);
    *(uint2*)(lo + (size_t)i4) = make_uint2(*(unsigned*)&lp0, *(unsigned*)&lp1);
}

// transpose [b][256][1024] -> split [b][1024][256]   (for channel-mix B operand)
__global__ void transpose_split_kernel(const float* __restrict__ in,
                                       __nv_bfloat16* __restrict__ hi,
                                       __nv_bfloat16* __restrict__ lo)
{
    __shared__ float t[32][33];
    const int b  = blockIdx.z;
    const int c0 = blockIdx.y * 32;     // over 256
    const int s0 = blockIdx.x * 32;     // over 1024
    const float* ib = in + (size_t)b * 256 * 1024;
#pragma unroll
    for (int i = threadIdx.y; i < 32; i += 8)
        t[i][threadIdx.x] = ib[(size_t)(c0 + i) * 1024 + s0 + threadIdx.x];
    __syncthreads();
    const size_t ob = (size_t)b * 1024 * 256;
#pragma unroll
    for (int i = threadIdx.y; i < 32; i += 8) {
        const float v = t[threadIdx.x][i];
        __nv_bfloat16 h, l;
        split1(v, h, l);
        const size_t a = ob + (size_t)(s0 + i) * 256 + c0 + threadIdx.x;
        hi[a] = h; lo[a] = l;
    }
}

// ===========================================================================
// Tensor-core NT GEMM on pre-split bf16 operands, 3-term compensation:
// C = epi( (Ah+Al) @ (Bh+Bl)^T ) ~= Ah@Bh^T + Ah@Bl^T + Al@Bh^T
// Tiles 128x128x32, 256 threads (8 warps, 64x32 warp tiles), 3-stage cp.async,
// SW64-swizzled 64B smem rows. Batched via blockIdx.z strides.
// Requires: M%128==0, N%128==0, K%32==0, row strides 16B-aligned.
// ===========================================================================

#define LDSM4(r0, r1, r2, r3, addr)                                            \
    asm volatile("ldmatrix.sync.aligned.m8n8.x4.shared.b16 {%0,%1,%2,%3}, [%4];" \
                 : "=r"(r0), "=r"(r1), "=r"(r2), "=r"(r3) : "r"(addr))

#define MMA16816(d, a, b)                                                      \
    asm volatile("mma.sync.aligned.m16n8k16.row.col.f32.bf16.bf16.f32 "        \
                 "{%0,%1,%2,%3},{%4,%5,%6,%7},{%8,%9},{%0,%1,%2,%3};"          \
                 : "+f"(d[0]), "+f"(d[1]), "+f"(d[2]), "+f"(d[3])              \
                 : "r"(a[0]), "r"(a[1]), "r"(a[2]), "r"(a[3]),                 \
                   "r"(b[0]), "r"(b[1]))

#define CPA(dst, src)                                                          \
    asm volatile("cp.async.cg.shared.global [%0], [%1], 16;\n"                 \
                 :: "r"(dst), "l"(src))

#define STG_SZ   32768
#define A_LO_OFF 8192
#define B_HI_OFF 16384
#define B_LO_OFF 24576
#define NSTAGES  3
#define MMA_SMEM (NSTAGES * STG_SZ)

template <int EPI>
__global__ void __launch_bounds__(256) gemm_sp(
    const __nv_bfloat16* __restrict__ Ahi, const __nv_bfloat16* __restrict__ Alo,
    const __nv_bfloat16* __restrict__ Bhi, const __nv_bfloat16* __restrict__ Blo,
    const float* __restrict__ bias, float* __restrict__ C,
    int K, int lda, int ldb, int ldc,
    long sA, long sB, long sC)
{
    extern __shared__ char sm[];
    const int z = blockIdx.z;
    Ahi += (size_t)z * sA; Alo += (size_t)z * sA;
    Bhi += (size_t)z * sB; Blo += (size_t)z * sB;
    C   += (size_t)z * sC;

    const int tid  = threadIdx.x;
    const int lane = tid & 31;
    const int warp = tid >> 5;
    const int wm   = warp >> 2;
    const int wn   = warp & 3;
    const int bm   = blockIdx.y * 128;
    const int bn   = blockIdx.x * 128;

    float acc[4][4][4];
#pragma unroll
    for (int i = 0; i < 4; i++)
#pragma unroll
        for (int j = 0; j < 4; j++)
#pragma unroll
            for (int c = 0; c < 4; c++) acc[i][j][c] = 0.0f;

    // load mapping: thread t -> row t>>1, 16-element half (t&1)
    const int prow = tid >> 1;
    const int pk   = (tid & 1) << 4;
    const __nv_bfloat16* pAh = Ahi + (size_t)(bm + prow) * lda + pk;
    const __nv_bfloat16* pAl = Alo + (size_t)(bm + prow) * lda + pk;
    const __nv_bfloat16* pBh = Bhi + (size_t)(bn + prow) * ldb + pk;
    const __nv_bfloat16* pBl = Blo + (size_t)(bn + prow) * ldb + pk;

    // smem store offsets (bytes): 64B rows, SW64 swizzle
    const int swm  = ((prow >> 1) & 3) << 4;
    const int rowb = prow * 64;
    const int kb0  = (tid & 1) << 5;
    const int st0  = rowb + ((kb0 +  0) ^ swm);
    const int st1  = rowb + ((kb0 + 16) ^ swm);

    const unsigned smu = (unsigned)__cvta_generic_to_shared(sm);

#define ISSUE(sidx, bufi) do {                                                 \
        const int k0_ = (sidx) << 5;                                           \
        const unsigned b_ = smu + (bufi) * STG_SZ;                             \
        CPA(b_ + st0,            pAh + k0_);                                   \
        CPA(b_ + st1,            pAh + k0_ + 8);                               \
        CPA(b_ + A_LO_OFF + st0, pAl + k0_);                                   \
        CPA(b_ + A_LO_OFF + st1, pAl + k0_ + 8);                               \
        CPA(b_ + B_HI_OFF + st0, pBh + k0_);                                   \
        CPA(b_ + B_HI_OFF + st1, pBh + k0_ + 8);                               \
        CPA(b_ + B_LO_OFF + st0, pBl + k0_);                                   \
        CPA(b_ + B_LO_OFF + st1, pBl + k0_ + 8);                               \
    } while (0)

    const int nstage = K >> 5;

    // prologue: fill stages 0..NSTAGES-2
    ISSUE(0, 0);
    asm volatile("cp.async.commit_group;\n" ::: "memory");
    ISSUE(1, 1);
    asm volatile("cp.async.commit_group;\n" ::: "memory");

    for (int s = 0; s < nstage; s++) {
        asm volatile("cp.async.wait_group 1;\n" ::: "memory");
        __syncthreads();

        const unsigned stage = smu + (unsigned)((s % NSTAGES) * STG_SZ);
#pragma unroll
        for (int kk = 0; kk < 2; kk++) {
            unsigned Ahr[4][4], Alr[4][4];
#pragma unroll
            for (int mt = 0; mt < 4; mt++) {
                const int row = wm * 64 + mt * 16 + (lane & 15);
                const int kb  = kk * 32 + ((lane >> 4) << 4);
                const int off = row * 64 + (kb ^ (((row >> 1) & 3) << 4));
                LDSM4(Ahr[mt][0], Ahr[mt][1], Ahr[mt][2], Ahr[mt][3], stage + off);
                LDSM4(Alr[mt][0], Alr[mt][1], Alr[mt][2], Alr[mt][3], stage + A_LO_OFF + off);
            }
            unsigned Bhr[4][2], Blr[4][2];
#pragma unroll
            for (int np = 0; np < 2; np++) {
                const int row = wn * 32 + np * 16 + (lane & 7) + ((lane >> 4) << 3);
                const int kb  = kk * 32 + (((lane >> 3) & 1) << 4);
                const int off = row * 64 + (kb ^ (((row >> 1) & 3) << 4));
                unsigned r0, r1, r2, r3;
                LDSM4(r0, r1, r2, r3, stage + B_HI_OFF + off);
                Bhr[np * 2][0] = r0; Bhr[np * 2][1] = r1;
                Bhr[np * 2 + 1][0] = r2; Bhr[np * 2 + 1][1] = r3;
                LDSM4(r0, r1, r2, r3, stage + B_LO_OFF + off);
                Blr[np * 2][0] = r0; Blr[np * 2][1] = r1;
                Blr[np * 2 + 1][0] = r2; Blr[np * 2 + 1][1] = r3;
            }
#pragma unroll
            for (int mt = 0; mt < 4; mt++) {
#pragma unroll
                for (int nt = 0; nt < 4; nt++) {
                    MMA16816(acc[mt][nt], Ahr[mt], Bhr[nt]);
                    MMA16816(acc[mt][nt], Ahr[mt], Blr[nt]);
                    MMA16816(acc[mt][nt], Alr[mt], Bhr[nt]);
                }
            }
        }
        __syncthreads();

        const int sn = s + NSTAGES - 1;
        if (sn < nstage) ISSUE(sn, sn % NSTAGES);
        asm volatile("cp.async.commit_group;\n" ::: "memory");
    }

    // epilogue
#pragma unroll
    for (int mt = 0; mt < 4; mt++) {
#pragma unroll
        for (int nt = 0; nt < 4; nt++) {
            const int row0 = bm + wm * 64 + mt * 16 + (lane >> 2);
            const int col0 = bn + wn * 32 + nt * 8 + ((lane & 3) << 1);
            float b0 = 0.f, b1 = 0.f;
            if (EPI == EPI_BIAS_SILU || EPI == EPI_BIAS_SOFTPLUS) {
                b0 = bias[col0]; b1 = bias[col0 + 1];
            }
            float2 v;
            v.x = epi_apply<EPI>(acc[mt][nt][0], b0);
            v.y = epi_apply<EPI>(acc[mt][nt][1], b1);
            *(float2*)(C + (size_t)row0 * ldc + col0) = v;
            v.x = epi_apply<EPI>(acc[mt][nt][2], b0);
            v.y = epi_apply<EPI>(acc[mt][nt][3], b1);
            *(float2*)(C + (size_t)(row0 + 8) * ldc + col0) = v;
        }
    }
#undef ISSUE
}

// ===========================================================================
// Depthwise causal conv (k=4) along L + bias + silu.
// ===========================================================================
__global__ void conv_silu_kernel(const float* __restrict__ xz,
                                 const float* __restrict__ w,
                                 const float* __restrict__ cb,
                                 float* __restrict__ xi)
{
    const int idx = blockIdx.x * blockDim.x + threadIdx.x;
    const int d = idx & (DI - 1);
    const int b = idx >> 10;
    const float w0 = w[d * 4 + 0], w1 = w[d * 4 + 1];
    const float w2 = w[d * 4 + 2], w3 = w[d * 4 + 3];
    const float bias = cb[d];
    const float* xp = xz + (size_t)b * L_ * (2 * DI) + d;
    float*       yp = xi + (size_t)b * L_ * DI + d;
    float x0 = 0.f, x1 = 0.f, x2 = 0.f;
    for (int t = 0; t < L_; t++) {
        const float x3 = xp[(size_t)t * (2 * DI)];
        float v = fmaf(w0, x0, fmaf(w1, x1, fmaf(w2, x2, fmaf(w3, x3, bias))));
        yp[(size_t)t * DI] = v / (1.0f + expf(-v));
        x0 = x1; x1 = x2; x2 = x3;
    }
}

// ===========================================================================
// Selective scan: one thread per (b, d), 2 states, L=256 steps. dbl stride 128.
// ===========================================================================
__global__ void scan_kernel(const float* __restrict__ dt,
                            const float* __restrict__ xi,
                            const float* __restrict__ dbl,
                            const float* __restrict__ xz,
                            const float* __restrict__ Alog,
                            const float* __restrict__ Dp,
                            float* __restrict__ y)
{
    const int idx = blockIdx.x * blockDim.x + threadIdx.x;
    const int d = idx & (DI - 1);
    const int b = idx >> 10;
    const float A0 = -expf(Alog[d * 2 + 0]);
    const float A1 = -expf(Alog[d * 2 + 1]);
    const float Dd = Dp[d];
    const size_t rbase = (size_t)b * L_;
    float h0 = 0.f, h1 = 0.f;
    for (int t = 0; t < L_; t++) {
        const size_t r = rbase + t;
        const float dtv = dt[r * DI + d];
        const float xv  = xi[r * DI + d];
        const float zv  = xz[r * (2 * DI) + DI + d];
        const float* q  = dbl + r * DBLP + DTR;
        const float B0 = q[0], B1 = q[1], C0 = q[2], C1 = q[3];
        const float dx = dtv * xv;
        h0 = fmaf(expf(dtv * A0), h0, dx * B0);
        h1 = fmaf(expf(dtv * A1), h1, dx * B1);
        float yv = fmaf(h0, C0, fmaf(h1, C1, Dd * xv));
        yv *= zv / (1.0f + expf(-zv));
        y[r * DI + d] = yv;
    }
}

// ===========================================================================
// LayerNorm over last dim (1024), one block per row, eps = 1e-5.
// ===========================================================================
__global__ void ln_kernel(const float* __restrict__ in,
                          const float* __restrict__ g,
                          const float* __restrict__ bt,
                          float* __restrict__ out)
{
    const int row = blockIdx.x;
    const float* x = in  + (size_t)row * DM;
    float*       o = out + (size_t)row * DM;
    float v[4];
    float s = 0.f, s2 = 0.f;
#pragma unroll
    for (int i = 0; i < 4; i++) {
        v[i] = x[threadIdx.x + i * 256];
        s += v[i]; s2 += v[i] * v[i];
    }
#pragma unroll
    for (int off = 16; off > 0; off >>= 1) {
        s  += __shfl_down_sync(0xFFFFFFFFu, s,  off);
        s2 += __shfl_down_sync(0xFFFFFFFFu, s2, off);
    }
    __shared__ float rs[8], rs2[8];
    const int wid = threadIdx.x >> 5;
    if ((threadIdx.x & 31) == 0) { rs[wid] = s; rs2[wid] = s2; }
    __syncthreads();
    float ts = 0.f, ts2 = 0.f;
#pragma unroll
    for (int i = 0; i < 8; i++) { ts += rs[i]; ts2 += rs2[i]; }
    const float mean = ts * (1.0f / DM);
    const float var  = ts2 * (1.0f / DM) - mean * mean;
    const float inv  = rsqrtf(var + 1e-5f);
#pragma unroll
    for (int i = 0; i < 4; i++) {
        const int c = threadIdx.x + i * 256;
        o[c] = (v[i] - mean) * inv * g[c] + bt[c];
    }
}

__global__ void add_silu_kernel(const float* __restrict__ a,
                                const float* __restrict__ b,
                                float* __restrict__ o, int n)
{
    const int i = blockIdx.x * blockDim.x + threadIdx.x;
    if (i < n) {
        const float v = a[i] + b[i];
        o[i] = v / (1.0f + expf(-v));
    }
}

// ===========================================================================
// Host orchestration
// ===========================================================================
static inline void split_launch(const float* in, __nv_bfloat16* hi,
                                __nv_bfloat16* lo, int n) {
    split_kernel<<<(n / 4 + 255) / 256, 256>>>(in, hi, lo, n / 4);
}

struct Bufs {
    float *xz, *xi, *dblp, *dt, *y, *bufA, *bufB, *bufC;
    __nv_bfloat16 *Xh, *Xl, *Ah, *Al, *Wh, *Wl, *Dh, *Dl;
};

// run one mamba layer; input activation pre-split in (Inh, Inl)
static void run_mamba(const __nv_bfloat16* Inh, const __nv_bfloat16* Inl,
                      const float* Win, const float* convw, const float* convb,
                      const float* Wx, const float* Wdt, const float* bdt,
                      const float* Alog, const float* Dp, const float* Wout,
                      float* out, const Bufs& B)
{
    // xz = x @ Win^T : [4096, 2048]
    split_launch(Win, B.Wh, B.Wl, 2 * DI * DM);
    gemm_sp<EPI_NONE><<<dim3(16, 32), 256, MMA_SMEM>>>(
        Inh, Inl, B.Wh, B.Wl, nullptr, B.xz, DM, DM, DM, 2 * DI, 0, 0, 0);
    // xi = silu(causal conv + bias)
    conv_silu_kernel<<<(B_ * DI) / 256, 256>>>(B.xz, convw, convb, B.xi);
    // dblp = xi @ WxPad^T : [4096, 128]
    split_launch(B.xi, B.Ah, B.Al, BL * DI);
    split_pad_wx_kernel<<<128, 256>>>(Wx, B.Wh, B.Wl);
    gemm_sp<EPI_NONE><<<dim3(1, 32), 256, MMA_SMEM>>>(
        B.Ah, B.Al, B.Wh, B.Wl, nullptr, B.dblp, DI, DI, DI, DBLP, 0, 0, 0);
    // dt = softplus(dblp[:, :64] @ Wdt^T + bdt) : [4096, 1024]
    split_launch(B.dblp, B.Dh, B.Dl, BL * DBLP);
    split_launch(Wdt, B.Wh, B.Wl, DI * DTR);
    gemm_sp<EPI_BIAS_SOFTPLUS><<<dim3(8, 32), 256, MMA_SMEM>>>(
        B.Dh, B.Dl, B.Wh, B.Wl, bdt, B.dt, DTR, DBLP, DTR, DI, 0, 0, 0);
    // y = scan + gate
    scan_kernel<<<(B_ * DI) / 128, 128>>>(B.dt, B.xi, B.dblp, B.xz, Alog, Dp, B.y);
    // out = y @ Wout^T : [4096, 1024]
    split_launch(B.y, B.Ah, B.Al, BL * DI);
    split_launch(Wout, B.Wh, B.Wl, DM * DI);
    gemm_sp<EPI_NONE><<<dim3(8, 32), 256, MMA_SMEM>>>(
        B.Ah, B.Al, B.Wh, B.Wl, nullptr, out, DI, DI, DI, DM, 0, 0, 0);
}

extern "C" void kernel_launch(void* const* d_in, const int* in_sizes, int n_in,
                              void* d_out, int out_size)
{
    const float* x        = (const float*)d_in[0];
    const float* m1_Win   = (const float*)d_in[1];
    const float* m1_convw = (const float*)d_in[2];
    const float* m1_convb = (const float*)d_in[3];
    const float* m1_Wx    = (const float*)d_in[4];
    const float* m1_Wdt   = (const float*)d_in[5];
    const float* m1_bdt   = (const float*)d_in[6];
    const float* m1_Alog  = (const float*)d_in[7];
    const float* m1_D     = (const float*)d_in[8];
    const float* m1_Wout  = (const float*)d_in[9];
    const float* m2_Win   = (const float*)d_in[10];
    const float* m2_convw = (const float*)d_in[11];
    const float* m2_convb = (const float*)d_in[12];
    const float* m2_Wx    = (const float*)d_in[13];
    const float* m2_Wdt   = (const float*)d_in[14];
    const float* m2_bdt   = (const float*)d_in[15];
    const float* m2_Alog  = (const float*)d_in[16];
    const float* m2_D     = (const float*)d_in[17];
    const float* m2_Wout  = (const float*)d_in[18];
    const float* ln1_g    = (const float*)d_in[19];
    const float* ln1_b    = (const float*)d_in[20];
    const float* ln2_g    = (const float*)d_in[21];
    const float* ln2_b    = (const float*)d_in[22];
    const float* W_mid    = (const float*)d_in[23];
    const float* W_spa    = (const float*)d_in[24];
    const float* b_spa    = (const float*)d_in[25];
    const float* W_res    = (const float*)d_in[26];

    cudaFuncSetAttribute(gemm_sp<EPI_NONE>,
                         cudaFuncAttributeMaxDynamicSharedMemorySize, MMA_SMEM);
    cudaFuncSetAttribute(gemm_sp<EPI_SILU>,
                         cudaFuncAttributeMaxDynamicSharedMemorySize, MMA_SMEM);
    cudaFuncSetAttribute(gemm_sp<EPI_BIAS_SILU>,
                         cudaFuncAttributeMaxDynamicSharedMemorySize, MMA_SMEM);
    cudaFuncSetAttribute(gemm_sp<EPI_BIAS_SOFTPLUS>,
                         cudaFuncAttributeMaxDynamicSharedMemorySize, MMA_SMEM);

    Bufs B;
    cudaGetSymbolAddress((void**)&B.xz,   g_xz);
    cudaGetSymbolAddress((void**)&B.xi,   g_xi);
    cudaGetSymbolAddress((void**)&B.dblp, g_dblp);
    cudaGetSymbolAddress((void**)&B.dt,   g_dt);
    cudaGetSymbolAddress((void**)&B.y,    g_y);
    cudaGetSymbolAddress((void**)&B.bufA, g_bufA);
    cudaGetSymbolAddress((void**)&B.bufB, g_bufB);
    cudaGetSymbolAddress((void**)&B.bufC, g_bufC);
    cudaGetSymbolAddress((void**)&B.Xh,   g_Xh);
    cudaGetSymbolAddress((void**)&B.Xl,   g_Xl);
    cudaGetSymbolAddress((void**)&B.Ah,   g_Ah);
    cudaGetSymbolAddress((void**)&B.Al,   g_Al);
    cudaGetSymbolAddress((void**)&B.Wh,   g_Wh);
    cudaGetSymbolAddress((void**)&B.Wl,   g_Wl);
    cudaGetSymbolAddress((void**)&B.Dh,   g_Dh);
    cudaGetSymbolAddress((void**)&B.Dl,   g_Dl);

    // split original x (reused by mamba1 and W_spa gemm)
    split_launch(x, B.Xh, B.Xl, BL * DM);

    // s = mamba1(x)
    run_mamba(B.Xh, B.Xl, m1_Win, m1_convw, m1_convb, m1_Wx, m1_Wdt, m1_bdt,
              m1_Alog, m1_D, m1_Wout, B.bufA, B);
    // s = ln1(s)
    ln_kernel<<<BL, 256>>>(B.bufA, ln1_g, ln1_b, B.bufA);
    // s = silu(W_mid channel mix): out[b,o,s] = silu(sum_c W_mid[o,c] s[b,c,s])
    transpose_split_kernel<<<dim3(32, 8, B_), dim3(32, 8)>>>(B.bufA, B.Ah, B.Al);
    split_launch(W_mid, B.Wh, B.Wl, 256 * 256);
    gemm_sp<EPI_SILU><<<dim3(8, 2, B_), 256, MMA_SMEM>>>(
        B.Wh, B.Wl, B.Ah, B.Al, nullptr, B.bufB, 256, 256, 256, 1024,
        0, (long)1024 * 256, (long)256 * 1024);
    // s = mamba2(s)
    split_launch(B.bufB, B.Ah, B.Al, BL * DM);
    run_mamba(B.Ah, B.Al, m2_Win, m2_convw, m2_convb, m2_Wx, m2_Wdt, m2_bdt,
              m2_Alog, m2_D, m2_Wout, B.bufA, B);
    // s = ln2(s)
    ln_kernel<<<BL, 256>>>(B.bufA, ln2_g, ln2_b, B.bufA);
    // r = silu(x @ W_spa^T + b_spa)
    split_launch(W_spa, B.Wh, B.Wl, DM * DM);
    gemm_sp<EPI_BIAS_SILU><<<dim3(8, 32), 256, MMA_SMEM>>>(
        B.Xh, B.Xl, B.Wh, B.Wl, b_spa, B.bufC, DM, DM, DM, DM, 0, 0, 0);
    // r = silu(W_res channel mix)
    transpose_split_kernel<<<dim3(32, 8, B_), dim3(32, 8)>>>(B.bufC, B.Ah, B.Al);
    split_launch(W_res, B.Wh, B.Wl, 256 * 256);
    gemm_sp<EPI_SILU><<<dim3(8, 2, B_), 256, MMA_SMEM>>>(
        B.Wh, B.Wl, B.Ah, B.Al, nullptr, B.bufB, 256, 256, 256, 1024,
        0, (long)1024 * 256, (long)256 * 1024);
    // out = silu(s + r)
    add_silu_kernel<<<(BL * DM) / 256, 256>>>(B.bufA, B.bufB, (float*)d_out, BL * DM);
}

// round 9
// speedup vs baseline: 3.8020x; 1.4042x over previous
#include <cuda_runtime.h>
#include <cuda_bf16.h>
#include <math.h>

// Problem dims (fixed by the dataset)
#define B_    16
#define L_    256
#define DM    1024
#define DI    1024
#define DTR   64
#define BL    (B_ * L_)      // 4096 rows
#define DBLP  128            // padded dbl width (dtr=64 | B0 B1 C0 C1 | pad)
#define NCH   8              // scan chunks
#define CHL   32             // steps per chunk

// ---------------- scratch (static device globals; no allocation allowed) ---
__device__ float g_xz  [BL * 2 * DI];
__device__ float g_xi  [BL * DI];
__device__ float g_dblp[BL * DBLP];
__device__ float g_dt  [BL * DI];
__device__ float g_bufA[BL * DM];
__device__ float g_bufB[BL * DM];
__device__ float g_bufC[BL * DM];

// scan chunk state [b][chunk][d]
__device__ float g_S  [B_ * NCH * DI];
__device__ float g_q0 [B_ * NCH * DI];
__device__ float g_q1 [B_ * NCH * DI];
__device__ float g_h0 [B_ * NCH * DI];
__device__ float g_h1 [B_ * NCH * DI];

// bf16 split buffers
__device__ __nv_bfloat16 g_Xh[BL * DM], g_Xl[BL * DM];
__device__ __nv_bfloat16 g_Ah[BL * DM], g_Al[BL * DM];
__device__ __nv_bfloat16 g_Wh[2 * DI * DM], g_Wl[2 * DI * DM];
__device__ __nv_bfloat16 g_Dh[BL * DBLP], g_Dl[BL * DBLP];

// ---------------- epilogue modes ------------------------------------------
#define EPI_NONE          0
#define EPI_SILU          1
#define EPI_BIAS_SILU     2
#define EPI_BIAS_SOFTPLUS 3

template <int EPI>
__device__ __forceinline__ float epi_apply(float v, float bia) {
    if (EPI == EPI_BIAS_SILU || EPI == EPI_BIAS_SOFTPLUS) v += bia;
    if (EPI == EPI_SILU || EPI == EPI_BIAS_SILU) v = v / (1.0f + expf(-v));
    if (EPI == EPI_BIAS_SOFTPLUS) v = (v > 20.0f) ? v : log1pf(expf(v));
    return v;
}

// ---------------- split helpers -------------------------------------------
__device__ __forceinline__ void split1(float v, __nv_bfloat16& h, __nv_bfloat16& l) {
    h = __float2bfloat16_rn(v);
    l = __float2bfloat16_rn(v - __bfloat162float(h));
}

__device__ __forceinline__ unsigned pack2h(float a, float b) {
    __nv_bfloat162 p; p.x = __float2bfloat16_rn(a); p.y = __float2bfloat16_rn(b);
    return *(unsigned*)&p;
}

__global__ void split_kernel(const float* __restrict__ in,
                             __nv_bfloat16* __restrict__ hi,
                             __nv_bfloat16* __restrict__ lo, int n4)
{
    const int i = blockIdx.x * blockDim.x + threadIdx.x;
    if (i >= n4) return;
    const float4 v = *(const float4*)(in + 4 * (size_t)i);
    __nv_bfloat16 h0, h1, h2, h3, l0, l1, l2, l3;
    split1(v.x, h0, l0); split1(v.y, h1, l1);
    split1(v.z, h2, l2); split1(v.w, h3, l3);
    __nv_bfloat162 hp0; hp0.x = h0; hp0.y = h1;
    __nv_bfloat162 hp1; hp1.x = h2; hp1.y = h3;
    __nv_bfloat162 lp0; lp0.x = l0; lp0.y = l1;
    __nv_bfloat162 lp1; lp1.x = l2; lp1.y = l3;
    *(uint2*)(hi + 4 * (size_t)i) = make_uint2(*(unsigned*)&hp0, *(unsigned*)&hp1);
    *(uint2*)(lo + 4 * (size_t)i) = make_uint2(*(unsigned*)&lp0, *(unsigned*)&lp1);
}

// pad Wx [68,1024] -> [128,1024] split (rows >= 68 zero)
__global__ void split_pad_wx_kernel(const float* __restrict__ in,
                                    __nv_bfloat16* __restrict__ hi,
                                    __nv_bfloat16* __restrict__ lo)
{
    const int i = blockIdx.x * blockDim.x + threadIdx.x;
    const int i4 = i << 2;
    const int row = i4 >> 10;
    float4 v = make_float4(0.f, 0.f, 0.f, 0.f);
    if (row < 68) v = *(const float4*)(in + (size_t)row * 1024 + (i4 & 1023));
    __nv_bfloat16 h0, h1, h2, h3, l0, l1, l2, l3;
    split1(v.x, h0, l0); split1(v.y, h1, l1);
    split1(v.z, h2, l2); split1(v.w, h3, l3);
    __nv_bfloat162 hp0; hp0.x = h0; hp0.y = h1;
    __nv_bfloat162 hp1; hp1.x = h2; hp1.y = h3;
    __nv_bfloat162 lp0; lp0.x = l0; lp0.y = l1;
    __nv_bfloat162 lp1; lp1.x = l2; lp1.y = l3;
    *(uint2*)(hi + (size_t)i4) = make_uint2(*(unsigned*)&hp0, *(unsigned*)&hp1);
    *(uint2*)(lo + (size_t)i4) = make_uint2(*(unsigned*)&lp0, *(unsigned*)&lp1);
}

// transpose [b][256][1024] -> split [b][1024][256]
__global__ void transpose_split_kernel(const float* __restrict__ in,
                                       __nv_bfloat16* __restrict__ hi,
                                       __nv_bfloat16* __restrict__ lo)
{
    __shared__ float t[32][33];
    const int b  = blockIdx.z;
    const int c0 = blockIdx.y * 32;
    const int s0 = blockIdx.x * 32;
    const float* ib = in + (size_t)b * 256 * 1024;
#pragma unroll
    for (int i = threadIdx.y; i < 32; i += 8)
        t[i][threadIdx.x] = ib[(size_t)(c0 + i) * 1024 + s0 + threadIdx.x];
    __syncthreads();
    const size_t ob = (size_t)b * 1024 * 256;
#pragma unroll
    for (int i = threadIdx.y; i < 32; i += 8) {
        const float v = t[threadIdx.x][i];
        __nv_bfloat16 h, l;
        split1(v, h, l);
        const size_t a = ob + (size_t)(s0 + i) * 256 + c0 + threadIdx.x;
        hi[a] = h; lo[a] = l;
    }
}

// ===========================================================================
// Tensor-core NT GEMM on pre-split bf16 operands (3-term compensation).
// Optional WS: also write split bf16 output (hi/lo) alongside float C.
// ===========================================================================
#define LDSM4(r0, r1, r2, r3, addr)                                            \
    asm volatile("ldmatrix.sync.aligned.m8n8.x4.shared.b16 {%0,%1,%2,%3}, [%4];" \
                 : "=r"(r0), "=r"(r1), "=r"(r2), "=r"(r3) : "r"(addr))

#define MMA16816(d, a, b)                                                      \
    asm volatile("mma.sync.aligned.m16n8k16.row.col.f32.bf16.bf16.f32 "        \
                 "{%0,%1,%2,%3},{%4,%5,%6,%7},{%8,%9},{%0,%1,%2,%3};"          \
                 : "+f"(d[0]), "+f"(d[1]), "+f"(d[2]), "+f"(d[3])              \
                 : "r"(a[0]), "r"(a[1]), "r"(a[2]), "r"(a[3]),                 \
                   "r"(b[0]), "r"(b[1]))

#define CPA(dst, src)                                                          \
    asm volatile("cp.async.cg.shared.global [%0], [%1], 16;\n"                 \
                 :: "r"(dst), "l"(src))

#define STG_SZ   32768
#define A_LO_OFF 8192
#define B_HI_OFF 16384
#define B_LO_OFF 24576
#define NSTAGES  3
#define MMA_SMEM (NSTAGES * STG_SZ)

template <int EPI, int WS>
__global__ void __launch_bounds__(256) gemm_sp(
    const __nv_bfloat16* __restrict__ Ahi, const __nv_bfloat16* __restrict__ Alo,
    const __nv_bfloat16* __restrict__ Bhi, const __nv_bfloat16* __restrict__ Blo,
    const float* __restrict__ bias, float* __restrict__ C,
    __nv_bfloat16* __restrict__ Ohi, __nv_bfloat16* __restrict__ Olo,
    int K, int lda, int ldb, int ldc,
    long sA, long sB, long sC)
{
    extern __shared__ char sm[];
    const int z = blockIdx.z;
    Ahi += (size_t)z * sA; Alo += (size_t)z * sA;
    Bhi += (size_t)z * sB; Blo += (size_t)z * sB;
    C   += (size_t)z * sC;

    const int tid  = threadIdx.x;
    const int lane = tid & 31;
    const int warp = tid >> 5;
    const int wm   = warp >> 2;
    const int wn   = warp & 3;
    const int bm   = blockIdx.y * 128;
    const int bn   = blockIdx.x * 128;

    float acc[4][4][4];
#pragma unroll
    for (int i = 0; i < 4; i++)
#pragma unroll
        for (int j = 0; j < 4; j++)
#pragma unroll
            for (int c = 0; c < 4; c++) acc[i][j][c] = 0.0f;

    const int prow = tid >> 1;
    const int pk   = (tid & 1) << 4;
    const __nv_bfloat16* pAh = Ahi + (size_t)(bm + prow) * lda + pk;
    const __nv_bfloat16* pAl = Alo + (size_t)(bm + prow) * lda + pk;
    const __nv_bfloat16* pBh = Bhi + (size_t)(bn + prow) * ldb + pk;
    const __nv_bfloat16* pBl = Blo + (size_t)(bn + prow) * ldb + pk;

    const int swm  = ((prow >> 1) & 3) << 4;
    const int rowb = prow * 64;
    const int kb0  = (tid & 1) << 5;
    const int st0  = rowb + ((kb0 +  0) ^ swm);
    const int st1  = rowb + ((kb0 + 16) ^ swm);

    const unsigned smu = (unsigned)__cvta_generic_to_shared(sm);

#define ISSUE(sidx, bufi) do {                                                 \
        const int k0_ = (sidx) << 5;                                           \
        const unsigned b_ = smu + (bufi) * STG_SZ;                             \
        CPA(b_ + st0,            pAh + k0_);                                   \
        CPA(b_ + st1,            pAh + k0_ + 8);                               \
        CPA(b_ + A_LO_OFF + st0, pAl + k0_);                                   \
        CPA(b_ + A_LO_OFF + st1, pAl + k0_ + 8);                               \
        CPA(b_ + B_HI_OFF + st0, pBh + k0_);                                   \
        CPA(b_ + B_HI_OFF + st1, pBh + k0_ + 8);                               \
        CPA(b_ + B_LO_OFF + st0, pBl + k0_);                                   \
        CPA(b_ + B_LO_OFF + st1, pBl + k0_ + 8);                               \
    } while (0)

    const int nstage = K >> 5;

    ISSUE(0, 0);
    asm volatile("cp.async.commit_group;\n" ::: "memory");
    ISSUE(1, 1);
    asm volatile("cp.async.commit_group;\n" ::: "memory");

    for (int s = 0; s < nstage; s++) {
        asm volatile("cp.async.wait_group 1;\n" ::: "memory");
        __syncthreads();

        const unsigned stage = smu + (unsigned)((s % NSTAGES) * STG_SZ);
#pragma unroll
        for (int kk = 0; kk < 2; kk++) {
            unsigned Ahr[4][4], Alr[4][4];
#pragma unroll
            for (int mt = 0; mt < 4; mt++) {
                const int row = wm * 64 + mt * 16 + (lane & 15);
                const int kb  = kk * 32 + ((lane >> 4) << 4);
                const int off = row * 64 + (kb ^ (((row >> 1) & 3) << 4));
                LDSM4(Ahr[mt][0], Ahr[mt][1], Ahr[mt][2], Ahr[mt][3], stage + off);
                LDSM4(Alr[mt][0], Alr[mt][1], Alr[mt][2], Alr[mt][3], stage + A_LO_OFF + off);
            }
            unsigned Bhr[4][2], Blr[4][2];
#pragma unroll
            for (int np = 0; np < 2; np++) {
                const int row = wn * 32 + np * 16 + (lane & 7) + ((lane >> 4) << 3);
                const int kb  = kk * 32 + (((lane >> 3) & 1) << 4);
                const int off = row * 64 + (kb ^ (((row >> 1) & 3) << 4));
                unsigned r0, r1, r2, r3;
                LDSM4(r0, r1, r2, r3, stage + B_HI_OFF + off);
                Bhr[np * 2][0] = r0; Bhr[np * 2][1] = r1;
                Bhr[np * 2 + 1][0] = r2; Bhr[np * 2 + 1][1] = r3;
                LDSM4(r0, r1, r2, r3, stage + B_LO_OFF + off);
                Blr[np * 2][0] = r0; Blr[np * 2][1] = r1;
                Blr[np * 2 + 1][0] = r2; Blr[np * 2 + 1][1] = r3;
            }
#pragma unroll
            for (int mt = 0; mt < 4; mt++) {
#pragma unroll
                for (int nt = 0; nt < 4; nt++) {
                    MMA16816(acc[mt][nt], Ahr[mt], Bhr[nt]);
                    MMA16816(acc[mt][nt], Ahr[mt], Blr[nt]);
                    MMA16816(acc[mt][nt], Alr[mt], Bhr[nt]);
                }
            }
        }
        __syncthreads();

        const int sn = s + NSTAGES - 1;
        if (sn < nstage) ISSUE(sn, sn % NSTAGES);
        asm volatile("cp.async.commit_group;\n" ::: "memory");
    }

#pragma unroll
    for (int mt = 0; mt < 4; mt++) {
#pragma unroll
        for (int nt = 0; nt < 4; nt++) {
            const int row0 = bm + wm * 64 + mt * 16 + (lane >> 2);
            const int col0 = bn + wn * 32 + nt * 8 + ((lane & 3) << 1);
            float b0 = 0.f, b1 = 0.f;
            if (EPI == EPI_BIAS_SILU || EPI == EPI_BIAS_SOFTPLUS) {
                b0 = bias[col0]; b1 = bias[col0 + 1];
            }
#pragma unroll
            for (int half = 0; half < 2; half++) {
                const size_t row = (size_t)(row0 + half * 8);
                float2 v;
                v.x = epi_apply<EPI>(acc[mt][nt][2 * half + 0], b0);
                v.y = epi_apply<EPI>(acc[mt][nt][2 * half + 1], b1);
                *(float2*)(C + row * ldc + col0) = v;
                if (WS) {
                    __nv_bfloat16 hx, lx, hy, ly;
                    split1(v.x, hx, lx); split1(v.y, hy, ly);
                    __nv_bfloat162 hp; hp.x = hx; hp.y = hy;
                    __nv_bfloat162 lp; lp.x = lx; lp.y = ly;
                    *(unsigned*)(Ohi + row * ldc + col0) = *(unsigned*)&hp;
                    *(unsigned*)(Olo + row * ldc + col0) = *(unsigned*)&lp;
                }
            }
        }
    }
#undef ISSUE
}

// ===========================================================================
// Parallel depthwise causal conv (k=4) + bias + silu. One thread per (b,t,d4).
// Writes xi (float) AND its bf16 split (for the Wx GEMM).
// ===========================================================================
__global__ void conv_silu_kernel(const float* __restrict__ xz,
                                 const float* __restrict__ w,
                                 const float* __restrict__ cb,
                                 float* __restrict__ xi,
                                 __nv_bfloat16* __restrict__ xih,
                                 __nv_bfloat16* __restrict__ xil)
{
    const int idx = blockIdx.x * blockDim.x + threadIdx.x;  // BL*DI/4
    const int dq  = idx & 255;          // d/4
    const int r   = idx >> 8;           // b*256 + t
    const int t   = r & 255;
    const int d4  = dq << 2;

    const float* base = xz + (size_t)r * 2048 + d4;
    const float4 zf = make_float4(0.f, 0.f, 0.f, 0.f);
    const float4 x3 = *(const float4*)base;
    const float4 x2 = (t >= 1) ? *(const float4*)(base - 2048) : zf;
    const float4 x1 = (t >= 2) ? *(const float4*)(base - 4096) : zf;
    const float4 x0 = (t >= 3) ? *(const float4*)(base - 6144) : zf;

    const float4 wa = *(const float4*)(w + (size_t)(d4 + 0) * 4);
    const float4 wb = *(const float4*)(w + (size_t)(d4 + 1) * 4);
    const float4 wc = *(const float4*)(w + (size_t)(d4 + 2) * 4);
    const float4 wd = *(const float4*)(w + (size_t)(d4 + 3) * 4);
    const float4 bi = *(const float4*)(cb + d4);

    float4 v;
    v.x = fmaf(wa.x, x0.x, fmaf(wa.y, x1.x, fmaf(wa.z, x2.x, fmaf(wa.w, x3.x, bi.x))));
    v.y = fmaf(wb.x, x0.y, fmaf(wb.y, x1.y, fmaf(wb.z, x2.y, fmaf(wb.w, x3.y, bi.y))));
    v.z = fmaf(wc.x, x0.z, fmaf(wc.y, x1.z, fmaf(wc.z, x2.z, fmaf(wc.w, x3.z, bi.z))));
    v.w = fmaf(wd.x, x0.w, fmaf(wd.y, x1.w, fmaf(wd.z, x2.w, fmaf(wd.w, x3.w, bi.w))));
    v.x = v.x / (1.0f + expf(-v.x));
    v.y = v.y / (1.0f + expf(-v.y));
    v.z = v.z / (1.0f + expf(-v.z));
    v.w = v.w / (1.0f + expf(-v.w));

    *(float4*)(xi + (size_t)r * DI + d4) = v;

    __nv_bfloat16 h0, h1, h2, h3, l0, l1, l2, l3;
    split1(v.x, h0, l0); split1(v.y, h1, l1);
    split1(v.z, h2, l2); split1(v.w, h3, l3);
    __nv_bfloat162 hp0; hp0.x = h0; hp0.y = h1;
    __nv_bfloat162 hp1; hp1.x = h2; hp1.y = h3;
    __nv_bfloat162 lp0; lp0.x = l0; lp0.y = l1;
    __nv_bfloat162 lp1; lp1.x = l2; lp1.y = l3;
    *(uint2*)(xih + (size_t)r * DI + d4) = make_uint2(*(unsigned*)&hp0, *(unsigned*)&hp1);
    *(uint2*)(xil + (size_t)r * DI + d4) = make_uint2(*(unsigned*)&lp0, *(unsigned*)&lp1);
}

// ===========================================================================
// Chunked selective scan (8 chunks of 32 steps; 8x parallelism).
// h_t = exp(dt_t A) h_{t-1} + dt_t x_t B_t ; chunk transform (exp(A S), q).
// ===========================================================================
__global__ void scan_pass1(const float* __restrict__ dt,
                           const float* __restrict__ xi,
                           const float* __restrict__ dbl,
                           const float* __restrict__ Alog,
                           float* __restrict__ Sg,
                           float* __restrict__ q0g,
                           float* __restrict__ q1g)
{
    const int idx = blockIdx.x * blockDim.x + threadIdx.x;  // B_*NCH*DI
    const int d = idx & (DI - 1);
    const int c = (idx >> 10) & (NCH - 1);
    const int b = idx >> 13;
    const float A0 = -expf(Alog[d * 2 + 0]);
    const float A1 = -expf(Alog[d * 2 + 1]);
    const int r0 = b * L_ + c * CHL;
    float S = 0.f, q0 = 0.f, q1 = 0.f;
#pragma unroll 4
    for (int t = 0; t < CHL; t++) {
        const size_t r = (size_t)(r0 + t);
        const float dtv = dt[r * DI + d];
        const float xv  = xi[r * DI + d];
        const float B0 = dbl[r * DBLP + DTR + 0];
        const float B1 = dbl[r * DBLP + DTR + 1];
        S += dtv;
        const float dx = dtv * xv;
        q0 = fmaf(expf(dtv * A0), q0, dx * B0);
        q1 = fmaf(expf(dtv * A1), q1, dx * B1);
    }
    Sg[idx] = S; q0g[idx] = q0; q1g[idx] = q1;
}

__global__ void scan_pass2(const float* __restrict__ Alog,
                           const float* __restrict__ Sg,
                           const float* __restrict__ q0g,
                           const float* __restrict__ q1g,
                           float* __restrict__ h0g,
                           float* __restrict__ h1g)
{
    const int tid = blockIdx.x * blockDim.x + threadIdx.x;  // B_*DI
    const int d = tid & (DI - 1);
    const int b = tid >> 10;
    const float A0 = -expf(Alog[d * 2 + 0]);
    const float A1 = -expf(Alog[d * 2 + 1]);
    float h0 = 0.f, h1 = 0.f;
#pragma unroll
    for (int c = 0; c < NCH; c++) {
        const int i = ((b * NCH + c) << 10) + d;
        h0g[i] = h0; h1g[i] = h1;
        h0 = fmaf(expf(A0 * Sg[i]), h0, q0g[i]);
        h1 = fmaf(expf(A1 * Sg[i]), h1, q1g[i]);
    }
}

// pass3: replay each chunk from its true h_in; write gated output as bf16 split
__global__ void scan_pass3(const float* __restrict__ dt,
                           const float* __restrict__ xi,
                           const float* __restrict__ dbl,
                           const float* __restrict__ xz,
                           const float* __restrict__ Alog,
                           const float* __restrict__ Dp,
                           const float* __restrict__ h0g,
                           const float* __restrict__ h1g,
                           __nv_bfloat16* __restrict__ yh,
                           __nv_bfloat16* __restrict__ yl)
{
    const int idx = blockIdx.x * blockDim.x + threadIdx.x;  // B_*NCH*DI
    const int d = idx & (DI - 1);
    const int c = (idx >> 10) & (NCH - 1);
    const int b = idx >> 13;
    const float A0 = -expf(Alog[d * 2 + 0]);
    const float A1 = -expf(Alog[d * 2 + 1]);
    const float Dd = Dp[d];
    const int r0 = b * L_ + c * CHL;
    float h0 = h0g[idx], h1 = h1g[idx];
#pragma unroll 4
    for (int t = 0; t < CHL; t++) {
        const size_t r = (size_t)(r0 + t);
        const float dtv = dt[r * DI + d];
        const float xv  = xi[r * DI + d];
        const float zv  = xz[r * (2 * DI) + DI + d];
        const float B0 = dbl[r * DBLP + DTR + 0];
        const float B1 = dbl[r * DBLP + DTR + 1];
        const float C0 = dbl[r * DBLP + DTR + 2];
        const float C1 = dbl[r * DBLP + DTR + 3];
        const float dx = dtv * xv;
        h0 = fmaf(expf(dtv * A0), h0, dx * B0);
        h1 = fmaf(expf(dtv * A1), h1, dx * B1);
        float yv = fmaf(h0, C0, fmaf(h1, C1, Dd * xv));
        yv *= zv / (1.0f + expf(-zv));
        __nv_bfloat16 h, l;
        split1(yv, h, l);
        yh[r * DI + d] = h;
        yl[r * DI + d] = l;
    }
}

// ===========================================================================
// LayerNorm over last dim (1024), one block per row, eps = 1e-5.
// ===========================================================================
__global__ void ln_kernel(const float* __restrict__ in,
                          const float* __restrict__ g,
                          const float* __restrict__ bt,
                          float* __restrict__ out)
{
    const int row = blockIdx.x;
    const float* x = in  + (size_t)row * DM;
    float*       o = out + (size_t)row * DM;
    float v[4];
    float s = 0.f, s2 = 0.f;
#pragma unroll
    for (int i = 0; i < 4; i++) {
        v[i] = x[threadIdx.x + i * 256];
        s += v[i]; s2 += v[i] * v[i];
    }
#pragma unroll
    for (int off = 16; off > 0; off >>= 1) {
        s  += __shfl_down_sync(0xFFFFFFFFu, s,  off);
        s2 += __shfl_down_sync(0xFFFFFFFFu, s2, off);
    }
    __shared__ float rs[8], rs2[8];
    const int wid = threadIdx.x >> 5;
    if ((threadIdx.x & 31) == 0) { rs[wid] = s; rs2[wid] = s2; }
    __syncthreads();
    float ts = 0.f, ts2 = 0.f;
#pragma unroll
    for (int i = 0; i < 8; i++) { ts += rs[i]; ts2 += rs2[i]; }
    const float mean = ts * (1.0f / DM);
    const float var  = ts2 * (1.0f / DM) - mean * mean;
    const float inv  = rsqrtf(var + 1e-5f);
#pragma unroll
    for (int i = 0; i < 4; i++) {
        const int c = threadIdx.x + i * 256;
        o[c] = (v[i] - mean) * inv * g[c] + bt[c];
    }
}

__global__ void add_silu_kernel(const float* __restrict__ a,
                                const float* __restrict__ b,
                                float* __restrict__ o, int n)
{
    const int i = blockIdx.x * blockDim.x + threadIdx.x;
    if (i < n) {
        const float v = a[i] + b[i];
        o[i] = v / (1.0f + expf(-v));
    }
}

// ===========================================================================
// Host orchestration
// ===========================================================================
static inline void split_launch(const float* in, __nv_bfloat16* hi,
                                __nv_bfloat16* lo, int n) {
    split_kernel<<<(n / 4 + 255) / 256, 256>>>(in, hi, lo, n / 4);
}

struct Bufs {
    float *xz, *xi, *dblp, *dt, *bufA, *bufB, *bufC;
    float *S, *q0, *q1, *h0, *h1;
    __nv_bfloat16 *Xh, *Xl, *Ah, *Al, *Wh, *Wl, *Dh, *Dl;
};

static void run_mamba(const __nv_bfloat16* Inh, const __nv_bfloat16* Inl,
                      const float* Win, const float* convw, const float* convb,
                      const float* Wx, const float* Wdt, const float* bdt,
                      const float* Alog, const float* Dp, const float* Wout,
                      float* out, const Bufs& B)
{
    // xz = x @ Win^T : [4096, 2048]
    split_launch(Win, B.Wh, B.Wl, 2 * DI * DM);
    gemm_sp<EPI_NONE, 0><<<dim3(16, 32), 256, MMA_SMEM>>>(
        Inh, Inl, B.Wh, B.Wl, nullptr, B.xz, nullptr, nullptr,
        DM, DM, DM, 2 * DI, 0, 0, 0);
    // xi = silu(conv + bias)  (+ fused split into Ah/Al)
    conv_silu_kernel<<<BL * DI / 4 / 256, 256>>>(B.xz, convw, convb, B.xi, B.Ah, B.Al);
    // dblp = xi @ WxPad^T : [4096, 128]  (+ fused split into Dh/Dl)
    split_pad_wx_kernel<<<128, 256>>>(Wx, B.Wh, B.Wl);
    gemm_sp<EPI_NONE, 1><<<dim3(1, 32), 256, MMA_SMEM>>>(
        B.Ah, B.Al, B.Wh, B.Wl, nullptr, B.dblp, B.Dh, B.Dl,
        DI, DI, DI, DBLP, 0, 0, 0);
    // dt = softplus(dblp[:, :64] @ Wdt^T + bdt) : [4096, 1024]
    split_launch(Wdt, B.Wh, B.Wl, DI * DTR);
    gemm_sp<EPI_BIAS_SOFTPLUS, 0><<<dim3(8, 32), 256, MMA_SMEM>>>(
        B.Dh, B.Dl, B.Wh, B.Wl, bdt, B.dt, nullptr, nullptr,
        DTR, DBLP, DTR, DI, 0, 0, 0);
    // chunked scan (+ fused y split into Ah/Al)
    scan_pass1<<<B_ * NCH * DI / 256, 256>>>(B.dt, B.xi, B.dblp, Alog,
                                             B.S, B.q0, B.q1);
    scan_pass2<<<B_ * DI / 256, 256>>>(Alog, B.S, B.q0, B.q1, B.h0, B.h1);
    scan_pass3<<<B_ * NCH * DI / 256, 256>>>(B.dt, B.xi, B.dblp, B.xz, Alog, Dp,
                                             B.h0, B.h1, B.Ah, B.Al);
    // out = y @ Wout^T : [4096, 1024]
    split_launch(Wout, B.Wh, B.Wl, DM * DI);
    gemm_sp<EPI_NONE, 0><<<dim3(8, 32), 256, MMA_SMEM>>>(
        B.Ah, B.Al, B.Wh, B.Wl, nullptr, out, nullptr, nullptr,
        DI, DI, DI, DM, 0, 0, 0);
}

extern "C" void kernel_launch(void* const* d_in, const int* in_sizes, int n_in,
                              void* d_out, int out_size)
{
    const float* x        = (const float*)d_in[0];
    const float* m1_Win   = (const float*)d_in[1];
    const float* m1_convw = (const float*)d_in[2];
    const float* m1_convb = (const float*)d_in[3];
    const float* m1_Wx    = (const float*)d_in[4];
    const float* m1_Wdt   = (const float*)d_in[5];
    const float* m1_bdt   = (const float*)d_in[6];
    const float* m1_Alog  = (const float*)d_in[7];
    const float* m1_D     = (const float*)d_in[8];
    const float* m1_Wout  = (const float*)d_in[9];
    const float* m2_Win   = (const float*)d_in[10];
    const float* m2_convw = (const float*)d_in[11];
    const float* m2_convb = (const float*)d_in[12];
    const float* m2_Wx    = (const float*)d_in[13];
    const float* m2_Wdt   = (const float*)d_in[14];
    const float* m2_bdt   = (const float*)d_in[15];
    const float* m2_Alog  = (const float*)d_in[16];
    const float* m2_D     = (const float*)d_in[17];
    const float* m2_Wout  = (const float*)d_in[18];
    const float* ln1_g    = (const float*)d_in[19];
    const float* ln1_b    = (const float*)d_in[20];
    const float* ln2_g    = (const float*)d_in[21];
    const float* ln2_b    = (const float*)d_in[22];
    const float* W_mid    = (const float*)d_in[23];
    const float* W_spa    = (const float*)d_in[24];
    const float* b_spa    = (const float*)d_in[25];
    const float* W_res    = (const float*)d_in[26];

    cudaFuncSetAttribute(gemm_sp<EPI_NONE, 0>,
                         cudaFuncAttributeMaxDynamicSharedMemorySize, MMA_SMEM);
    cudaFuncSetAttribute(gemm_sp<EPI_NONE, 1>,
                         cudaFuncAttributeMaxDynamicSharedMemorySize, MMA_SMEM);
    cudaFuncSetAttribute(gemm_sp<EPI_SILU, 0>,
                         cudaFuncAttributeMaxDynamicSharedMemorySize, MMA_SMEM);
    cudaFuncSetAttribute(gemm_sp<EPI_BIAS_SILU, 0>,
                         cudaFuncAttributeMaxDynamicSharedMemorySize, MMA_SMEM);
    cudaFuncSetAttribute(gemm_sp<EPI_BIAS_SOFTPLUS, 0>,
                         cudaFuncAttributeMaxDynamicSharedMemorySize, MMA_SMEM);

    Bufs B;
    cudaGetSymbolAddress((void**)&B.xz,   g_xz);
    cudaGetSymbolAddress((void**)&B.xi,   g_xi);
    cudaGetSymbolAddress((void**)&B.dblp, g_dblp);
    cudaGetSymbolAddress((void**)&B.dt,   g_dt);
    cudaGetSymbolAddress((void**)&B.bufA, g_bufA);
    cudaGetSymbolAddress((void**)&B.bufB, g_bufB);
    cudaGetSymbolAddress((void**)&B.bufC, g_bufC);
    cudaGetSymbolAddress((void**)&B.S,    g_S);
    cudaGetSymbolAddress((void**)&B.q0,   g_q0);
    cudaGetSymbolAddress((void**)&B.q1,   g_q1);
    cudaGetSymbolAddress((void**)&B.h0,   g_h0);
    cudaGetSymbolAddress((void**)&B.h1,   g_h1);
    cudaGetSymbolAddress((void**)&B.Xh,   g_Xh);
    cudaGetSymbolAddress((void**)&B.Xl,   g_Xl);
    cudaGetSymbolAddress((void**)&B.Ah,   g_Ah);
    cudaGetSymbolAddress((void**)&B.Al,   g_Al);
    cudaGetSymbolAddress((void**)&B.Wh,   g_Wh);
    cudaGetSymbolAddress((void**)&B.Wl,   g_Wl);
    cudaGetSymbolAddress((void**)&B.Dh,   g_Dh);
    cudaGetSymbolAddress((void**)&B.Dl,   g_Dl);

    // split original x (reused by mamba1 and W_spa gemm)
    split_launch(x, B.Xh, B.Xl, BL * DM);

    // s = mamba1(x)
    run_mamba(B.Xh, B.Xl, m1_Win, m1_convw, m1_convb, m1_Wx, m1_Wdt, m1_bdt,
              m1_Alog, m1_D, m1_Wout, B.bufA, B);
    // s = ln1(s)
    ln_kernel<<<BL, 256>>>(B.bufA, ln1_g, ln1_b, B.bufA);
    // s = silu(W_mid channel mix)
    transpose_split_kernel<<<dim3(32, 8, B_), dim3(32, 8)>>>(B.bufA, B.Ah, B.Al);
    split_launch(W_mid, B.Wh, B.Wl, 256 * 256);
    gemm_sp<EPI_SILU, 0><<<dim3(8, 2, B_), 256, MMA_SMEM>>>(
        B.Wh, B.Wl, B.Ah, B.Al, nullptr, B.bufB, nullptr, nullptr,
        256, 256, 256, 1024, 0, (long)1024 * 256, (long)256 * 1024);
    // s = mamba2(s)
    split_launch(B.bufB, B.Ah, B.Al, BL * DM);
    run_mamba(B.Ah, B.Al, m2_Win, m2_convw, m2_convb, m2_Wx, m2_Wdt, m2_bdt,
              m2_Alog, m2_D, m2_Wout, B.bufA, B);
    // s = ln2(s)
    ln_kernel<<<BL, 256>>>(B.bufA, ln2_g, ln2_b, B.bufA);
    // r = silu(x @ W_spa^T + b_spa)
    split_launch(W_spa, B.Wh, B.Wl, DM * DM);
    gemm_sp<EPI_BIAS_SILU, 0><<<dim3(8, 32), 256, MMA_SMEM>>>(
        B.Xh, B.Xl, B.Wh, B.Wl, b_spa, B.bufC, nullptr, nullptr,
        DM, DM, DM, DM, 0, 0, 0);
    // r = silu(W_res channel mix)
    transpose_split_kernel<<<dim3(32, 8, B_), dim3(32, 8)>>>(B.bufC, B.Ah, B.Al);
    split_launch(W_res, B.Wh, B.Wl, 256 * 256);
    gemm_sp<EPI_SILU, 0><<<dim3(8, 2, B_), 256, MMA_SMEM>>>(
        B.Wh, B.Wl, B.Ah, B.Al, nullptr, B.bufB, nullptr, nullptr,
        256, 256, 256, 1024, 0, (long)1024 * 256, (long)256 * 1024);
    // out = silu(s + r)
    add_silu_kernel<<<(BL * DM) / 256, 256>>>(B.bufA, B.bufB, (float*)d_out, BL * DM);
}

// round 15
// speedup vs baseline: 4.1630x; 1.0950x over previous
#include <cuda_runtime.h>
#include <cuda_bf16.h>
#include <math.h>

// Problem dims (fixed by the dataset)
#define B_    16
#define L_    256
#define DM    1024
#define DI    1024
#define DTR   64
#define BL    (B_ * L_)      // 4096 rows
#define DBLP  128            // padded dbl width (dtr=64 | B0 B1 C0 C1 | pad)
#define NCH   8              // scan chunks
#define CHL   32             // steps per chunk

// ---------------- scratch (static device globals; no allocation allowed) ---
__device__ float g_xz  [BL * 2 * DI];
__device__ float g_xi  [BL * DI];
__device__ float g_dblp[BL * DBLP];
__device__ float g_dt  [BL * DI];
__device__ float g_bufA[BL * DM];
__device__ float g_bufB[BL * DM];
__device__ float g_bufC[BL * DM];

// scan chunk state [b][chunk][d]
__device__ float g_S  [B_ * NCH * DI];
__device__ float g_q0 [B_ * NCH * DI];
__device__ float g_q1 [B_ * NCH * DI];
__device__ float g_h0 [B_ * NCH * DI];
__device__ float g_h1 [B_ * NCH * DI];

// bf16 split buffers
__device__ __nv_bfloat16 g_Xh[BL * DM], g_Xl[BL * DM];
__device__ __nv_bfloat16 g_Ah[BL * DM], g_Al[BL * DM];
__device__ __nv_bfloat16 g_Wh[2 * DI * DM], g_Wl[2 * DI * DM];
__device__ __nv_bfloat16 g_Dh[BL * DBLP], g_Dl[BL * DBLP];

// ---------------- epilogue modes ------------------------------------------
#define EPI_NONE          0
#define EPI_SILU          1
#define EPI_BIAS_SILU     2
#define EPI_BIAS_SOFTPLUS 3

template <int EPI>
__device__ __forceinline__ float epi_apply(float v, float bia) {
    if (EPI == EPI_BIAS_SILU || EPI == EPI_BIAS_SOFTPLUS) v += bia;
    if (EPI == EPI_SILU || EPI == EPI_BIAS_SILU) v = v / (1.0f + expf(-v));
    if (EPI == EPI_BIAS_SOFTPLUS) v = (v > 20.0f) ? v : log1pf(expf(v));
    return v;
}

// ---------------- split helpers -------------------------------------------
__device__ __forceinline__ void split1(float v, __nv_bfloat16& h, __nv_bfloat16& l) {
    h = __float2bfloat16_rn(v);
    l = __float2bfloat16_rn(v - __bfloat162float(h));
}

__global__ void split_kernel(const float* __restrict__ in,
                             __nv_bfloat16* __restrict__ hi,
                             __nv_bfloat16* __restrict__ lo, int n4)
{
    const int i = blockIdx.x * blockDim.x + threadIdx.x;
    if (i >= n4) return;
    const float4 v = *(const float4*)(in + 4 * (size_t)i);
    __nv_bfloat16 h0, h1, h2, h3, l0, l1, l2, l3;
    split1(v.x, h0, l0); split1(v.y, h1, l1);
    split1(v.z, h2, l2); split1(v.w, h3, l3);
    __nv_bfloat162 hp0; hp0.x = h0; hp0.y = h1;
    __nv_bfloat162 hp1; hp1.x = h2; hp1.y = h3;
    __nv_bfloat162 lp0; lp0.x = l0; lp0.y = l1;
    __nv_bfloat162 lp1; lp1.x = l2; lp1.y = l3;
    *(uint2*)(hi + 4 * (size_t)i) = make_uint2(*(unsigned*)&hp0, *(unsigned*)&hp1);
    *(uint2*)(lo + 4 * (size_t)i) = make_uint2(*(unsigned*)&lp0, *(unsigned*)&lp1);
}

// pad Wx [68,1024] -> [128,1024] split (rows >= 68 zero)
__global__ void split_pad_wx_kernel(const float* __restrict__ in,
                                    __nv_bfloat16* __restrict__ hi,
                                    __nv_bfloat16* __restrict__ lo)
{
    const int i = blockIdx.x * blockDim.x + threadIdx.x;
    const int i4 = i << 2;
    const int row = i4 >> 10;
    float4 v = make_float4(0.f, 0.f, 0.f, 0.f);
    if (row < 68) v = *(const float4*)(in + (size_t)row * 1024 + (i4 & 1023));
    __nv_bfloat16 h0, h1, h2, h3, l0, l1, l2, l3;
    split1(v.x, h0, l0); split1(v.y, h1, l1);
    split1(v.z, h2, l2); split1(v.w, h3, l3);
    __nv_bfloat162 hp0; hp0.x = h0; hp0.y = h1;
    __nv_bfloat162 hp1; hp1.x = h2; hp1.y = h3;
    __nv_bfloat162 lp0; lp0.x = l0; lp0.y = l1;
    __nv_bfloat162 lp1; lp1.x = l2; lp1.y = l3;
    *(uint2*)(hi + (size_t)i4) = make_uint2(*(unsigned*)&hp0, *(unsigned*)&hp1);
    *(uint2*)(lo + (size_t)i4) = make_uint2(*(unsigned*)&lp0, *(unsigned*)&lp1);
}

// transpose [b][256][1024] -> split [b][1024][256]
__global__ void transpose_split_kernel(const float* __restrict__ in,
                                       __nv_bfloat16* __restrict__ hi,
                                       __nv_bfloat16* __restrict__ lo)
{
    __shared__ float t[32][33];
    const int b  = blockIdx.z;
    const int c0 = blockIdx.y * 32;
    const int s0 = blockIdx.x * 32;
    const float* ib = in + (size_t)b * 256 * 1024;
#pragma unroll
    for (int i = threadIdx.y; i < 32; i += 8)
        t[i][threadIdx.x] = ib[(size_t)(c0 + i) * 1024 + s0 + threadIdx.x];
    __syncthreads();
    const size_t ob = (size_t)b * 1024 * 256;
#pragma unroll
    for (int i = threadIdx.y; i < 32; i += 8) {
        const float v = t[threadIdx.x][i];
        __nv_bfloat16 h, l;
        split1(v, h, l);
        const size_t a = ob + (size_t)(s0 + i) * 256 + c0 + threadIdx.x;
        hi[a] = h; lo[a] = l;
    }
}

// reduce 4 K-split partials of the Wx GEMM -> dblp (float) + Dh/Dl (bf16 split)
__global__ void reduce_wx_kernel(const float* __restrict__ part,
                                 float* __restrict__ dblp,
                                 __nv_bfloat16* __restrict__ Dh,
                                 __nv_bfloat16* __restrict__ Dl)
{
    const int i = blockIdx.x * blockDim.x + threadIdx.x;   // BL*DBLP/4
    const size_t i4 = (size_t)i << 2;
    const size_t st = (size_t)BL * DBLP;
    const float4 a = *(const float4*)(part + i4);
    const float4 b = *(const float4*)(part + st + i4);
    const float4 c = *(const float4*)(part + 2 * st + i4);
    const float4 d = *(const float4*)(part + 3 * st + i4);
    float4 v;
    v.x = (a.x + b.x) + (c.x + d.x);
    v.y = (a.y + b.y) + (c.y + d.y);
    v.z = (a.z + b.z) + (c.z + d.z);
    v.w = (a.w + b.w) + (c.w + d.w);
    *(float4*)(dblp + i4) = v;
    __nv_bfloat16 h0, h1, h2, h3, l0, l1, l2, l3;
    split1(v.x, h0, l0); split1(v.y, h1, l1);
    split1(v.z, h2, l2); split1(v.w, h3, l3);
    __nv_bfloat162 hp0; hp0.x = h0; hp0.y = h1;
    __nv_bfloat162 hp1; hp1.x = h2; hp1.y = h3;
    __nv_bfloat162 lp0; lp0.x = l0; lp0.y = l1;
    __nv_bfloat162 lp1; lp1.x = l2; lp1.y = l3;
    *(uint2*)(Dh + i4) = make_uint2(*(unsigned*)&hp0, *(unsigned*)&hp1);
    *(uint2*)(Dl + i4) = make_uint2(*(unsigned*)&lp0, *(unsigned*)&lp1);
}

// ===========================================================================
// Tensor-core NT GEMM (legacy mma.sync path — tcgen05 is not available at
// .target sm_103) on pre-split bf16 operands, 3-term compensation:
// C = epi( (Ah+Al) @ (Bh+Bl)^T ) ~= Ah@Bh^T + Ah@Bl^T + Al@Bh^T
// Tiles 128x128x32, 256 threads (8 warps, 64x32 warp tiles), 3-stage cp.async,
// SW64-swizzled 64B smem rows. Batched / K-split via blockIdx.z flat offsets.
// __launch_bounds__(256, 2): regs capped at 128 -> 2 CTAs/SM (16 warps).
// Mainloop keeps only per-mt A fragments live to fit the register budget.
// ===========================================================================
#define LDSM4(r0, r1, r2, r3, addr)                                            \
    asm volatile("ldmatrix.sync.aligned.m8n8.x4.shared.b16 {%0,%1,%2,%3}, [%4];" \
                 : "=r"(r0), "=r"(r1), "=r"(r2), "=r"(r3) : "r"(addr))

#define MMA16816(d, a, b)                                                      \
    asm volatile("mma.sync.aligned.m16n8k16.row.col.f32.bf16.bf16.f32 "        \
                 "{%0,%1,%2,%3},{%4,%5,%6,%7},{%8,%9},{%0,%1,%2,%3};"          \
                 : "+f"(d[0]), "+f"(d[1]), "+f"(d[2]), "+f"(d[3])              \
                 : "r"(a[0]), "r"(a[1]), "r"(a[2]), "r"(a[3]),                 \
                   "r"(b[0]), "r"(b[1]))

#define CPA(dst, src)                                                          \
    asm volatile("cp.async.cg.shared.global [%0], [%1], 16;\n"                 \
                 :: "r"(dst), "l"(src))

#define STG_SZ   32768
#define A_LO_OFF 8192
#define B_HI_OFF 16384
#define B_LO_OFF 24576
#define NSTAGES  3
#define MMA_SMEM (NSTAGES * STG_SZ)

template <int EPI, int WS>
__global__ void __launch_bounds__(256, 2) gemm_sp(
    const __nv_bfloat16* __restrict__ Ahi, const __nv_bfloat16* __restrict__ Alo,
    const __nv_bfloat16* __restrict__ Bhi, const __nv_bfloat16* __restrict__ Blo,
    const float* __restrict__ bias, float* __restrict__ C,
    __nv_bfloat16* __restrict__ Ohi, __nv_bfloat16* __restrict__ Olo,
    int K, int lda, int ldb, int ldc,
    long sA, long sB, long sC)
{
    extern __shared__ char sm[];
    const int z = blockIdx.z;
    Ahi += (size_t)z * sA; Alo += (size_t)z * sA;
    Bhi += (size_t)z * sB; Blo += (size_t)z * sB;
    C   += (size_t)z * sC;

    const int tid  = threadIdx.x;
    const int lane = tid & 31;
    const int warp = tid >> 5;
    const int wm   = warp >> 2;
    const int wn   = warp & 3;
    const int bm   = blockIdx.y * 128;
    const int bn   = blockIdx.x * 128;

    float acc[4][4][4];
#pragma unroll
    for (int i = 0; i < 4; i++)
#pragma unroll
        for (int j = 0; j < 4; j++)
#pragma unroll
            for (int c = 0; c < 4; c++) acc[i][j][c] = 0.0f;

    // load mapping: thread t -> row t>>1, 16-element half (t&1)
    const int prow = tid >> 1;
    const int pk   = (tid & 1) << 4;
    const __nv_bfloat16* pAh = Ahi + (size_t)(bm + prow) * lda + pk;
    const __nv_bfloat16* pAl = Alo + (size_t)(bm + prow) * lda + pk;
    const __nv_bfloat16* pBh = Bhi + (size_t)(bn + prow) * ldb + pk;
    const __nv_bfloat16* pBl = Blo + (size_t)(bn + prow) * ldb + pk;

    // smem store offsets (bytes): 64B rows, SW64 swizzle
    const int swm  = ((prow >> 1) & 3) << 4;
    const int rowb = prow * 64;
    const int kb0  = (tid & 1) << 5;
    const int st0  = rowb + ((kb0 +  0) ^ swm);
    const int st1  = rowb + ((kb0 + 16) ^ swm);

    const unsigned smu = (unsigned)__cvta_generic_to_shared(sm);

#define ISSUE(sidx, bufi) do {                                                 \
        const int k0_ = (sidx) << 5;                                           \
        const unsigned b_ = smu + (bufi) * STG_SZ;                             \
        CPA(b_ + st0,            pAh + k0_);                                   \
        CPA(b_ + st1,            pAh + k0_ + 8);                               \
        CPA(b_ + A_LO_OFF + st0, pAl + k0_);                                   \
        CPA(b_ + A_LO_OFF + st1, pAl + k0_ + 8);                               \
        CPA(b_ + B_HI_OFF + st0, pBh + k0_);                                   \
        CPA(b_ + B_HI_OFF + st1, pBh + k0_ + 8);                               \
        CPA(b_ + B_LO_OFF + st0, pBl + k0_);                                   \
        CPA(b_ + B_LO_OFF + st1, pBl + k0_ + 8);                               \
    } while (0)

    const int nstage = K >> 5;

    ISSUE(0, 0);
    asm volatile("cp.async.commit_group;\n" ::: "memory");
    if (nstage > 1) ISSUE(1, 1);
    asm volatile("cp.async.commit_group;\n" ::: "memory");

    for (int s = 0; s < nstage; s++) {
        if (nstage > 1) asm volatile("cp.async.wait_group 1;\n" ::: "memory");
        else            asm volatile("cp.async.wait_group 0;\n" ::: "memory");
        __syncthreads();

        const unsigned stage = smu + (unsigned)((s % NSTAGES) * STG_SZ);
#pragma unroll
        for (int kk = 0; kk < 2; kk++) {
            // B fragments for all 4 nt tiles (hi + lo): 16 regs live
            unsigned Bhr[4][2], Blr[4][2];
#pragma unroll
            for (int np = 0; np < 2; np++) {
                const int row = wn * 32 + np * 16 + (lane & 7) + ((lane >> 4) << 3);
                const int kb  = kk * 32 + (((lane >> 3) & 1) << 4);
                const int off = row * 64 + (kb ^ (((row >> 1) & 3) << 4));
                unsigned r0, r1, r2, r3;
                LDSM4(r0, r1, r2, r3, stage + B_HI_OFF + off);
                Bhr[np * 2][0] = r0; Bhr[np * 2][1] = r1;
                Bhr[np * 2 + 1][0] = r2; Bhr[np * 2 + 1][1] = r3;
                LDSM4(r0, r1, r2, r3, stage + B_LO_OFF + off);
                Blr[np * 2][0] = r0; Blr[np * 2][1] = r1;
                Blr[np * 2 + 1][0] = r2; Blr[np * 2 + 1][1] = r3;
            }
            // A fragments transient per mt tile: 8 regs live at a time
#pragma unroll
            for (int mt = 0; mt < 4; mt++) {
                const int row = wm * 64 + mt * 16 + (lane & 15);
                const int kb  = kk * 32 + ((lane >> 4) << 4);
                const int off = row * 64 + (kb ^ (((row >> 1) & 3) << 4));
                unsigned Ahr[4], Alr[4];
                LDSM4(Ahr[0], Ahr[1], Ahr[2], Ahr[3], stage + off);
                LDSM4(Alr[0], Alr[1], Alr[2], Alr[3], stage + A_LO_OFF + off);
#pragma unroll
                for (int nt = 0; nt < 4; nt++) {
                    MMA16816(acc[mt][nt], Ahr, Bhr[nt]);
                    MMA16816(acc[mt][nt], Ahr, Blr[nt]);
                    MMA16816(acc[mt][nt], Alr, Bhr[nt]);
                }
            }
        }
        __syncthreads();

        const int sn = s + NSTAGES - 1;
        if (sn < nstage) ISSUE(sn, sn % NSTAGES);
        asm volatile("cp.async.commit_group;\n" ::: "memory");
    }

    // epilogue
#pragma unroll
    for (int mt = 0; mt < 4; mt++) {
#pragma unroll
        for (int nt = 0; nt < 4; nt++) {
            const int row0 = bm + wm * 64 + mt * 16 + (lane >> 2);
            const int col0 = bn + wn * 32 + nt * 8 + ((lane & 3) << 1);
            float b0 = 0.f, b1 = 0.f;
            if (EPI == EPI_BIAS_SILU || EPI == EPI_BIAS_SOFTPLUS) {
                b0 = bias[col0]; b1 = bias[col0 + 1];
            }
#pragma unroll
            for (int half = 0; half < 2; half++) {
                const size_t row = (size_t)(row0 + half * 8);
                float2 v;
                v.x = epi_apply<EPI>(acc[mt][nt][2 * half + 0], b0);
                v.y = epi_apply<EPI>(acc[mt][nt][2 * half + 1], b1);
                *(float2*)(C + row * ldc + col0) = v;
                if (WS) {
                    __nv_bfloat16 hx, lx, hy, ly;
                    split1(v.x, hx, lx); split1(v.y, hy, ly);
                    __nv_bfloat162 hp; hp.x = hx; hp.y = hy;
                    __nv_bfloat162 lp; lp.x = lx; lp.y = ly;
                    *(unsigned*)(Ohi + row * ldc + col0) = *(unsigned*)&hp;
                    *(unsigned*)(Olo + row * ldc + col0) = *(unsigned*)&lp;
                }
            }
        }
    }
#undef ISSUE
}

// ===========================================================================
// Parallel depthwise causal conv (k=4) + bias + silu. One thread per (b,t,d4).
// ===========================================================================
__global__ void conv_silu_kernel(const float* __restrict__ xz,
                                 const float* __restrict__ w,
                                 const float* __restrict__ cb,
                                 float* __restrict__ xi,
                                 __nv_bfloat16* __restrict__ xih,
                                 __nv_bfloat16* __restrict__ xil)
{
    const int idx = blockIdx.x * blockDim.x + threadIdx.x;
    const int dq  = idx & 255;
    const int r   = idx >> 8;
    const int t   = r & 255;
    const int d4  = dq << 2;

    const float* base = xz + (size_t)r * 2048 + d4;
    const float4 zf = make_float4(0.f, 0.f, 0.f, 0.f);
    const float4 x3 = *(const float4*)base;
    const float4 x2 = (t >= 1) ? *(const float4*)(base - 2048) : zf;
    const float4 x1 = (t >= 2) ? *(const float4*)(base - 4096) : zf;
    const float4 x0 = (t >= 3) ? *(const float4*)(base - 6144) : zf;

    const float4 wa = *(const float4*)(w + (size_t)(d4 + 0) * 4);
    const float4 wb = *(const float4*)(w + (size_t)(d4 + 1) * 4);
    const float4 wc = *(const float4*)(w + (size_t)(d4 + 2) * 4);
    const float4 wd = *(const float4*)(w + (size_t)(d4 + 3) * 4);
    const float4 bi = *(const float4*)(cb + d4);

    float4 v;
    v.x = fmaf(wa.x, x0.x, fmaf(wa.y, x1.x, fmaf(wa.z, x2.x, fmaf(wa.w, x3.x, bi.x))));
    v.y = fmaf(wb.x, x0.y, fmaf(wb.y, x1.y, fmaf(wb.z, x2.y, fmaf(wb.w, x3.y, bi.y))));
    v.z = fmaf(wc.x, x0.z, fmaf(wc.y, x1.z, fmaf(wc.z, x2.z, fmaf(wc.w, x3.z, bi.z))));
    v.w = fmaf(wd.x, x0.w, fmaf(wd.y, x1.w, fmaf(wd.z, x2.w, fmaf(wd.w, x3.w, bi.w))));
    v.x = v.x / (1.0f + expf(-v.x));
    v.y = v.y / (1.0f + expf(-v.y));
    v.z = v.z / (1.0f + expf(-v.z));
    v.w = v.w / (1.0f + expf(-v.w));

    *(float4*)(xi + (size_t)r * DI + d4) = v;

    __nv_bfloat16 h0, h1, h2, h3, l0, l1, l2, l3;
    split1(v.x, h0, l0); split1(v.y, h1, l1);
    split1(v.z, h2, l2); split1(v.w, h3, l3);
    __nv_bfloat162 hp0; hp0.x = h0; hp0.y = h1;
    __nv_bfloat162 hp1; hp1.x = h2; hp1.y = h3;
    __nv_bfloat162 lp0; lp0.x = l0; lp0.y = l1;
    __nv_bfloat162 lp1; lp1.x = l2; lp1.y = l3;
    *(uint2*)(xih + (size_t)r * DI + d4) = make_uint2(*(unsigned*)&hp0, *(unsigned*)&hp1);
    *(uint2*)(xil + (size_t)r * DI + d4) = make_uint2(*(unsigned*)&lp0, *(unsigned*)&lp1);
}

// ===========================================================================
// Chunked selective scan (8 chunks of 32 steps).
// ===========================================================================
__global__ void scan_pass1(const float* __restrict__ dt,
                           const float* __restrict__ xi,
                           const float* __restrict__ dbl,
                           const float* __restrict__ Alog,
                           float* __restrict__ Sg,
                           float* __restrict__ q0g,
                           float* __restrict__ q1g)
{
    const int idx = blockIdx.x * blockDim.x + threadIdx.x;
    const int d = idx & (DI - 1);
    const int c = (idx >> 10) & (NCH - 1);
    const int b = idx >> 13;
    const float A0 = -expf(Alog[d * 2 + 0]);
    const float A1 = -expf(Alog[d * 2 + 1]);
    const int r0 = b * L_ + c * CHL;
    float S = 0.f, q0 = 0.f, q1 = 0.f;
#pragma unroll 4
    for (int t = 0; t < CHL; t++) {
        const size_t r = (size_t)(r0 + t);
        const float dtv = dt[r * DI + d];
        const float xv  = xi[r * DI + d];
        const float B0 = dbl[r * DBLP + DTR + 0];
        const float B1 = dbl[r * DBLP + DTR + 1];
        S += dtv;
        const float dx = dtv * xv;
        q0 = fmaf(expf(dtv * A0), q0, dx * B0);
        q1 = fmaf(expf(dtv * A1), q1, dx * B1);
    }
    Sg[idx] = S; q0g[idx] = q0; q1g[idx] = q1;
}

__global__ void scan_pass2(const float* __restrict__ Alog,
                           const float* __restrict__ Sg,
                           const float* __restrict__ q0g,
                           const float* __restrict__ q1g,
                           float* __restrict__ h0g,
                           float* __restrict__ h1g)
{
    const int tid = blockIdx.x * blockDim.x + threadIdx.x;
    const int d = tid & (DI - 1);
    const int b = tid >> 10;
    const float A0 = -expf(Alog[d * 2 + 0]);
    const float A1 = -expf(Alog[d * 2 + 1]);
    float h0 = 0.f, h1 = 0.f;
#pragma unroll
    for (int c = 0; c < NCH; c++) {
        const int i = ((b * NCH + c) << 10) + d;
        h0g[i] = h0; h1g[i] = h1;
        h0 = fmaf(expf(A0 * Sg[i]), h0, q0g[i]);
        h1 = fmaf(expf(A1 * Sg[i]), h1, q1g[i]);
    }
}

__global__ void scan_pass3(const float* __restrict__ dt,
                           const float* __restrict__ xi,
                           const float* __restrict__ dbl,
                           const float* __restrict__ xz,
                           const float* __restrict__ Alog,
                           const float* __restrict__ Dp,
                           const float* __restrict__ h0g,
                           const float* __restrict__ h1g,
                           __nv_bfloat16* __restrict__ yh,
                           __nv_bfloat16* __restrict__ yl)
{
    const int idx = blockIdx.x * blockDim.x + threadIdx.x;
    const int d = idx & (DI - 1);
    const int c = (idx >> 10) & (NCH - 1);
    const int b = idx >> 13;
    const float A0 = -expf(Alog[d * 2 + 0]);
    const float A1 = -expf(Alog[d * 2 + 1]);
    const float Dd = Dp[d];
    const int r0 = b * L_ + c * CHL;
    float h0 = h0g[idx], h1 = h1g[idx];
#pragma unroll 4
    for (int t = 0; t < CHL; t++) {
        const size_t r = (size_t)(r0 + t);
        const float dtv = dt[r * DI + d];
        const float xv  = xi[r * DI + d];
        const float zv  = xz[r * (2 * DI) + DI + d];
        const float B0 = dbl[r * DBLP + DTR + 0];
        const float B1 = dbl[r * DBLP + DTR + 1];
        const float C0 = dbl[r * DBLP + DTR + 2];
        const float C1 = dbl[r * DBLP + DTR + 3];
        const float dx = dtv * xv;
        h0 = fmaf(expf(dtv * A0), h0, dx * B0);
        h1 = fmaf(expf(dtv * A1), h1, dx * B1);
        float yv = fmaf(h0, C0, fmaf(h1, C1, Dd * xv));
        yv *= zv / (1.0f + expf(-zv));
        __nv_bfloat16 h, l;
        split1(yv, h, l);
        yh[r * DI + d] = h;
        yl[r * DI + d] = l;
    }
}

// ===========================================================================
// LayerNorm over last dim (1024), one block per row, eps = 1e-5.
// ===========================================================================
__global__ void ln_kernel(const float* __restrict__ in,
                          const float* __restrict__ g,
                          const float* __restrict__ bt,
                          float* __restrict__ out)
{
    const int row = blockIdx.x;
    const float* x = in  + (size_t)row * DM;
    float*       o = out + (size_t)row * DM;
    float v[4];
    float s = 0.f, s2 = 0.f;
#pragma unroll
    for (int i = 0; i < 4; i++) {
        v[i] = x[threadIdx.x + i * 256];
        s += v[i]; s2 += v[i] * v[i];
    }
#pragma unroll
    for (int off = 16; off > 0; off >>= 1) {
        s  += __shfl_down_sync(0xFFFFFFFFu, s,  off);
        s2 += __shfl_down_sync(0xFFFFFFFFu, s2, off);
    }
    __shared__ float rs[8], rs2[8];
    const int wid = threadIdx.x >> 5;
    if ((threadIdx.x & 31) == 0) { rs[wid] = s; rs2[wid] = s2; }
    __syncthreads();
    float ts = 0.f, ts2 = 0.f;
#pragma unroll
    for (int i = 0; i < 8; i++) { ts += rs[i]; ts2 += rs2[i]; }
    const float mean = ts * (1.0f / DM);
    const float var  = ts2 * (1.0f / DM) - mean * mean;
    const float inv  = rsqrtf(var + 1e-5f);
#pragma unroll
    for (int i = 0; i < 4; i++) {
        const int c = threadIdx.x + i * 256;
        o[c] = (v[i] - mean) * inv * g[c] + bt[c];
    }
}

__global__ void add_silu_kernel(const float* __restrict__ a,
                                const float* __restrict__ b,
                                float* __restrict__ o, int n)
{
    const int i = blockIdx.x * blockDim.x + threadIdx.x;
    if (i < n) {
        const float v = a[i] + b[i];
        o[i] = v / (1.0f + expf(-v));
    }
}

// ===========================================================================
// Host orchestration
// ===========================================================================
static inline void split_launch(const float* in, __nv_bfloat16* hi,
                                __nv_bfloat16* lo, int n) {
    split_kernel<<<(n / 4 + 255) / 256, 256>>>(in, hi, lo, n / 4);
}

struct Bufs {
    float *xz, *xi, *dblp, *dt, *bufA, *bufB, *bufC;
    float *S, *q0, *q1, *h0, *h1;
    __nv_bfloat16 *Xh, *Xl, *Ah, *Al, *Wh, *Wl, *Dh, *Dl;
};

static void run_mamba(const __nv_bfloat16* Inh, const __nv_bfloat16* Inl,
                      const float* Win, const float* convw, const float* convb,
                      const float* Wx, const float* Wdt, const float* bdt,
                      const float* Alog, const float* Dp, const float* Wout,
                      float* out, const Bufs& B)
{
    // xz = x @ Win^T : [4096, 2048]
    split_launch(Win, B.Wh, B.Wl, 2 * DI * DM);
    gemm_sp<EPI_NONE, 0><<<dim3(16, 32), 256, MMA_SMEM>>>(
        Inh, Inl, B.Wh, B.Wl, nullptr, B.xz, nullptr, nullptr,
        DM, DM, DM, 2 * DI, 0, 0, 0);
    // xi = silu(conv + bias)  (+ fused split into Ah/Al)
    conv_silu_kernel<<<BL * DI / 4 / 256, 256>>>(B.xz, convw, convb, B.xi, B.Ah, B.Al);
    // dblp = xi @ WxPad^T : [4096, 128], K-split x4 for chip utilization
    // (partials in bufC; reduce fuses float out + bf16 split into Dh/Dl)
    split_pad_wx_kernel<<<128, 256>>>(Wx, B.Wh, B.Wl);
    gemm_sp<EPI_NONE, 0><<<dim3(1, 32, 4), 256, MMA_SMEM>>>(
        B.Ah, B.Al, B.Wh, B.Wl, nullptr, B.bufC, nullptr, nullptr,
        DI / 4, DI, DI, DBLP, DI / 4, DI / 4, (long)BL * DBLP);
    reduce_wx_kernel<<<BL * DBLP / 4 / 256, 256>>>(B.bufC, B.dblp, B.Dh, B.Dl);
    // dt = softplus(dblp[:, :64] @ Wdt^T + bdt) : [4096, 1024]
    split_launch(Wdt, B.Wh, B.Wl, DI * DTR);
    gemm_sp<EPI_BIAS_SOFTPLUS, 0><<<dim3(8, 32), 256, MMA_SMEM>>>(
        B.Dh, B.Dl, B.Wh, B.Wl, bdt, B.dt, nullptr, nullptr,
        DTR, DBLP, DTR, DI, 0, 0, 0);
    // chunked scan (+ fused y split into Ah/Al)
    scan_pass1<<<B_ * NCH * DI / 256, 256>>>(B.dt, B.xi, B.dblp, Alog,
                                             B.S, B.q0, B.q1);
    scan_pass2<<<B_ * DI / 256, 256>>>(Alog, B.S, B.q0, B.q1, B.h0, B.h1);
    scan_pass3<<<B_ * NCH * DI / 256, 256>>>(B.dt, B.xi, B.dblp, B.xz, Alog, Dp,
                                             B.h0, B.h1, B.Ah, B.Al);
    // out = y @ Wout^T : [4096, 1024]
    split_launch(Wout, B.Wh, B.Wl, DM * DI);
    gemm_sp<EPI_NONE, 0><<<dim3(8, 32), 256, MMA_SMEM>>>(
        B.Ah, B.Al, B.Wh, B.Wl, nullptr, out, nullptr, nullptr,
        DI, DI, DI, DM, 0, 0, 0);
}

extern "C" void kernel_launch(void* const* d_in, const int* in_sizes, int n_in,
                              void* d_out, int out_size)
{
    const float* x        = (const float*)d_in[0];
    const float* m1_Win   = (const float*)d_in[1];
    const float* m1_convw = (const float*)d_in[2];
    const float* m1_convb = (const float*)d_in[3];
    const float* m1_Wx    = (const float*)d_in[4];
    const float* m1_Wdt   = (const float*)d_in[5];
    const float* m1_bdt   = (const float*)d_in[6];
    const float* m1_Alog  = (const float*)d_in[7];
    const float* m1_D     = (const float*)d_in[8];
    const float* m1_Wout  = (const float*)d_in[9];
    const float* m2_Win   = (const float*)d_in[10];
    const float* m2_convw = (const float*)d_in[11];
    const float* m2_convb = (const float*)d_in[12];
    const float* m2_Wx    = (const float*)d_in[13];
    const float* m2_Wdt   = (const float*)d_in[14];
    const float* m2_bdt   = (const float*)d_in[15];
    const float* m2_Alog  = (const float*)d_in[16];
    const float* m2_D     = (const float*)d_in[17];
    const float* m2_Wout  = (const float*)d_in[18];
    const float* ln1_g    = (const float*)d_in[19];
    const float* ln1_b    = (const float*)d_in[20];
    const float* ln2_g    = (const float*)d_in[21];
    const float* ln2_b    = (const float*)d_in[22];
    const float* W_mid    = (const float*)d_in[23];
    const float* W_spa    = (const float*)d_in[24];
    const float* b_spa    = (const float*)d_in[25];
    const float* W_res    = (const float*)d_in[26];

    cudaFuncSetAttribute(gemm_sp<EPI_NONE, 0>,
                         cudaFuncAttributeMaxDynamicSharedMemorySize, MMA_SMEM);
    cudaFuncSetAttribute(gemm_sp<EPI_SILU, 0>,
                         cudaFuncAttributeMaxDynamicSharedMemorySize, MMA_SMEM);
    cudaFuncSetAttribute(gemm_sp<EPI_BIAS_SILU, 0>,
                         cudaFuncAttributeMaxDynamicSharedMemorySize, MMA_SMEM);
    cudaFuncSetAttribute(gemm_sp<EPI_BIAS_SOFTPLUS, 0>,
                         cudaFuncAttributeMaxDynamicSharedMemorySize, MMA_SMEM);

    Bufs B;
    cudaGetSymbolAddress((void**)&B.xz,   g_xz);
    cudaGetSymbolAddress((void**)&B.xi,   g_xi);
    cudaGetSymbolAddress((void**)&B.dblp, g_dblp);
    cudaGetSymbolAddress((void**)&B.dt,   g_dt);
    cudaGetSymbolAddress((void**)&B.bufA, g_bufA);
    cudaGetSymbolAddress((void**)&B.bufB, g_bufB);
    cudaGetSymbolAddress((void**)&B.bufC, g_bufC);
    cudaGetSymbolAddress((void**)&B.S,    g_S);
    cudaGetSymbolAddress((void**)&B.q0,   g_q0);
    cudaGetSymbolAddress((void**)&B.q1,   g_q1);
    cudaGetSymbolAddress((void**)&B.h0,   g_h0);
    cudaGetSymbolAddress((void**)&B.h1,   g_h1);
    cudaGetSymbolAddress((void**)&B.Xh,   g_Xh);
    cudaGetSymbolAddress((void**)&B.Xl,   g_Xl);
    cudaGetSymbolAddress((void**)&B.Ah,   g_Ah);
    cudaGetSymbolAddress((void**)&B.Al,   g_Al);
    cudaGetSymbolAddress((void**)&B.Wh,   g_Wh);
    cudaGetSymbolAddress((void**)&B.Wl,   g_Wl);
    cudaGetSymbolAddress((void**)&B.Dh,   g_Dh);
    cudaGetSymbolAddress((void**)&B.Dl,   g_Dl);

    // split original x (reused by mamba1 and W_spa gemm)
    split_launch(x, B.Xh, B.Xl, BL * DM);

    // s = mamba1(x)
    run_mamba(B.Xh, B.Xl, m1_Win, m1_convw, m1_convb, m1_Wx, m1_Wdt, m1_bdt,
              m1_Alog, m1_D, m1_Wout, B.bufA, B);
    // s = ln1(s)
    ln_kernel<<<BL, 256>>>(B.bufA, ln1_g, ln1_b, B.bufA);
    // s = silu(W_mid channel mix)
    transpose_split_kernel<<<dim3(32, 8, B_), dim3(32, 8)>>>(B.bufA, B.Ah, B.Al);
    split_launch(W_mid, B.Wh, B.Wl, 256 * 256);
    gemm_sp<EPI_SILU, 0><<<dim3(8, 2, B_), 256, MMA_SMEM>>>(
        B.Wh, B.Wl, B.Ah, B.Al, nullptr, B.bufB, nullptr, nullptr,
        256, 256, 256, 1024, 0, (long)1024 * 256, (long)256 * 1024);
    // s = mamba2(s)
    split_launch(B.bufB, B.Ah, B.Al, BL * DM);
    run_mamba(B.Ah, B.Al, m2_Win, m2_convw, m2_convb, m2_Wx, m2_Wdt, m2_bdt,
              m2_Alog, m2_D, m2_Wout, B.bufA, B);
    // s = ln2(s)
    ln_kernel<<<BL, 256>>>(B.bufA, ln2_g, ln2_b, B.bufA);
    // r = silu(x @ W_spa^T + b_spa)
    split_launch(W_spa, B.Wh, B.Wl, DM * DM);
    gemm_sp<EPI_BIAS_SILU, 0><<<dim3(8, 32), 256, MMA_SMEM>>>(
        B.Xh, B.Xl, B.Wh, B.Wl, b_spa, B.bufC, nullptr, nullptr,
        DM, DM, DM, DM, 0, 0, 0);
    // r = silu(W_res channel mix)
    transpose_split_kernel<<<dim3(32, 8, B_), dim3(32, 8)>>>(B.bufC, B.Ah, B.Al);
    split_launch(W_res, B.Wh, B.Wl, 256 * 256);
    gemm_sp<EPI_SILU, 0><<<dim3(8, 2, B_), 256, MMA_SMEM>>>(
        B.Wh, B.Wl, B.Ah, B.Al, nullptr, B.bufB, nullptr, nullptr,
        256, 256, 256, 1024, 0, (long)1024 * 256, (long)256 * 1024);
    // out = silu(s + r)
    add_silu_kernel<<<(BL * DM) / 256, 256>>>(B.bufA, B.bufB, (float*)d_out, BL * DM);
}

// round 16
// speedup vs baseline: 4.4956x; 1.0799x over previous
#include <cuda_runtime.h>
#include <cuda_bf16.h>
#include <math.h>

// Problem dims (fixed by the dataset)
#define B_    16
#define L_    256
#define DM    1024
#define DI    1024
#define DTR   64
#define BL    (B_ * L_)      // 4096 rows
#define DBLP  128            // padded dbl width (dtr=64 | B0 B1 C0 C1 | pad)
#define NCH   8              // scan chunks
#define CHL   32             // steps per chunk

// ---------------- scratch (static device globals; no allocation allowed) ---
__device__ float g_xz  [BL * 2 * DI];
__device__ float g_xi  [BL * DI];
__device__ float g_dblp[BL * DBLP];
__device__ float g_dt  [BL * DI];     // also reused as Wx K-split partial buffer
__device__ float g_bufA[BL * DM];
__device__ float g_bufB[BL * DM];
__device__ float g_bufC[BL * DM];

// scan chunk state [b][chunk][d]
__device__ float g_S  [B_ * NCH * DI];
__device__ float g_q0 [B_ * NCH * DI];
__device__ float g_q1 [B_ * NCH * DI];
__device__ float g_h0 [B_ * NCH * DI];
__device__ float g_h1 [B_ * NCH * DI];

// activation bf16 split buffers
__device__ __nv_bfloat16 g_Xh[BL * DM], g_Xl[BL * DM];
__device__ __nv_bfloat16 g_Ah[BL * DM], g_Al[BL * DM];
__device__ __nv_bfloat16 g_Dh[BL * DBLP], g_Dl[BL * DBLP];

// ---------------- weight split arena (packed, fixed offsets) ---------------
#define OW_WIN1  0
#define OW_WX1   2097152
#define OW_WDT1  2228224
#define OW_WOUT1 2293760
#define OW_WIN2  3342336
#define OW_WX2   5439488
#define OW_WDT2  5570560
#define OW_WOUT2 5636096
#define OW_WMID  6684672
#define OW_WSPA  6750208
#define OW_WRES  7798784
#define OW_TOTAL 7864320
__device__ __nv_bfloat16 g_WAh[OW_TOTAL], g_WAl[OW_TOTAL];

// ---------------- epilogue modes ------------------------------------------
#define EPI_NONE          0
#define EPI_SILU          1
#define EPI_BIAS_SILU     2
#define EPI_BIAS_SOFTPLUS 3

template <int EPI>
__device__ __forceinline__ float epi_apply(float v, float bia) {
    if (EPI == EPI_BIAS_SILU || EPI == EPI_BIAS_SOFTPLUS) v += bia;
    if (EPI == EPI_SILU || EPI == EPI_BIAS_SILU) v = v / (1.0f + expf(-v));
    if (EPI == EPI_BIAS_SOFTPLUS) v = (v > 20.0f) ? v : log1pf(expf(v));
    return v;
}

// ---------------- split helpers -------------------------------------------
__device__ __forceinline__ void split1(float v, __nv_bfloat16& h, __nv_bfloat16& l) {
    h = __float2bfloat16_rn(v);
    l = __float2bfloat16_rn(v - __bfloat162float(h));
}

__device__ __forceinline__ void split_store4(float4 v, __nv_bfloat16* hi,
                                             __nv_bfloat16* lo, size_t off4e)
{
    __nv_bfloat16 h0, h1, h2, h3, l0, l1, l2, l3;
    split1(v.x, h0, l0); split1(v.y, h1, l1);
    split1(v.z, h2, l2); split1(v.w, h3, l3);
    __nv_bfloat162 hp0; hp0.x = h0; hp0.y = h1;
    __nv_bfloat162 hp1; hp1.x = h2; hp1.y = h3;
    __nv_bfloat162 lp0; lp0.x = l0; lp0.y = l1;
    __nv_bfloat162 lp1; lp1.x = l2; lp1.y = l3;
    *(uint2*)(hi + off4e) = make_uint2(*(unsigned*)&hp0, *(unsigned*)&hp1);
    *(uint2*)(lo + off4e) = make_uint2(*(unsigned*)&lp0, *(unsigned*)&lp1);
}

__global__ void split_kernel(const float* __restrict__ in,
                             __nv_bfloat16* __restrict__ hi,
                             __nv_bfloat16* __restrict__ lo, int n4)
{
    const int i = blockIdx.x * blockDim.x + threadIdx.x;
    if (i >= n4) return;
    split_store4(*(const float4*)(in + 4 * (size_t)i), hi, lo, (size_t)i << 2);
}

// ---- one-shot split of ALL weights into the packed arena ----
struct WSegArg {
    const float* src[11];
    int cum4[11];           // cumulative end, float4 units
};

__global__ void wsplit_all_kernel(WSegArg S,
                                  __nv_bfloat16* __restrict__ hi,
                                  __nv_bfloat16* __restrict__ lo)
{
    const int i = blockIdx.x * blockDim.x + threadIdx.x;
    if (i >= OW_TOTAL / 4) return;
    int s = 0;
#pragma unroll
    for (int k = 0; k < 10; k++) if (i >= S.cum4[k]) s = k + 1;
    const int base = s ? S.cum4[s - 1] : 0;
    const int l4 = i - base;
    float4 v;
    // segments 1 and 5 are Wx [68,1024] zero-padded to [128,1024]
    if (s == 1 || s == 5) {
        const int e = l4 << 2;
        const int row = e >> 10;
        v = (row < 68) ? *(const float4*)(S.src[s] + (size_t)row * 1024 + (e & 1023))
                       : make_float4(0.f, 0.f, 0.f, 0.f);
    } else {
        v = *(const float4*)(S.src[s] + ((size_t)l4 << 2));
    }
    split_store4(v, hi, lo, (size_t)i << 2);
}

// transpose [b][256][1024] -> split [b][1024][256]
__global__ void transpose_split_kernel(const float* __restrict__ in,
                                       __nv_bfloat16* __restrict__ hi,
                                       __nv_bfloat16* __restrict__ lo)
{
    __shared__ float t[32][33];
    const int b  = blockIdx.z;
    const int c0 = blockIdx.y * 32;
    const int s0 = blockIdx.x * 32;
    const float* ib = in + (size_t)b * 256 * 1024;
#pragma unroll
    for (int i = threadIdx.y; i < 32; i += 8)
        t[i][threadIdx.x] = ib[(size_t)(c0 + i) * 1024 + s0 + threadIdx.x];
    __syncthreads();
    const size_t ob = (size_t)b * 1024 * 256;
#pragma unroll
    for (int i = threadIdx.y; i < 32; i += 8) {
        const float v = t[threadIdx.x][i];
        __nv_bfloat16 h, l;
        split1(v, h, l);
        const size_t a = ob + (size_t)(s0 + i) * 256 + c0 + threadIdx.x;
        hi[a] = h; lo[a] = l;
    }
}

// reduce 4 K-split partials of the Wx GEMM -> dblp (float) + Dh/Dl (bf16 split)
__global__ void reduce_wx_kernel(const float* __restrict__ part,
                                 float* __restrict__ dblp,
                                 __nv_bfloat16* __restrict__ Dh,
                                 __nv_bfloat16* __restrict__ Dl)
{
    const int i = blockIdx.x * blockDim.x + threadIdx.x;
    const size_t i4 = (size_t)i << 2;
    const size_t st = (size_t)BL * DBLP;
    const float4 a = *(const float4*)(part + i4);
    const float4 b = *(const float4*)(part + st + i4);
    const float4 c = *(const float4*)(part + 2 * st + i4);
    const float4 d = *(const float4*)(part + 3 * st + i4);
    float4 v;
    v.x = (a.x + b.x) + (c.x + d.x);
    v.y = (a.y + b.y) + (c.y + d.y);
    v.z = (a.z + b.z) + (c.z + d.z);
    v.w = (a.w + b.w) + (c.w + d.w);
    *(float4*)(dblp + i4) = v;
    split_store4(v, Dh, Dl, i4);
}

// ===========================================================================
// Tensor-core NT GEMM (legacy mma.sync path; tcgen05 not available at
// .target sm_103) on pre-split bf16 operands, 3-term compensation:
// C = epi( (Ah+Al) @ (Bh+Bl)^T ) ~= Ah@Bh^T + Ah@Bl^T + Al@Bh^T
// Tiles 128x128x32, 256 threads, 3-stage cp.async, SW64-swizzled smem.
// ONE barrier per stage (top-of-stage sync alone is sufficient: buffer
// (s+2)%3 == (s-1)%3 was fully consumed before the stage-s top barrier).
// ===========================================================================
#define LDSM4(r0, r1, r2, r3, addr)                                            \
    asm volatile("ldmatrix.sync.aligned.m8n8.x4.shared.b16 {%0,%1,%2,%3}, [%4];" \
                 : "=r"(r0), "=r"(r1), "=r"(r2), "=r"(r3) : "r"(addr))

#define MMA16816(d, a, b)                                                      \
    asm volatile("mma.sync.aligned.m16n8k16.row.col.f32.bf16.bf16.f32 "        \
                 "{%0,%1,%2,%3},{%4,%5,%6,%7},{%8,%9},{%0,%1,%2,%3};"          \
                 : "+f"(d[0]), "+f"(d[1]), "+f"(d[2]), "+f"(d[3])              \
                 : "r"(a[0]), "r"(a[1]), "r"(a[2]), "r"(a[3]),                 \
                   "r"(b[0]), "r"(b[1]))

#define CPA(dst, src)                                                          \
    asm volatile("cp.async.cg.shared.global [%0], [%1], 16;\n"                 \
                 :: "r"(dst), "l"(src))

#define STG_SZ   32768
#define A_LO_OFF 8192
#define B_HI_OFF 16384
#define B_LO_OFF 24576
#define NSTAGES  3
#define MMA_SMEM (NSTAGES * STG_SZ)

template <int EPI, int WS>
__global__ void __launch_bounds__(256, 2) gemm_sp(
    const __nv_bfloat16* __restrict__ Ahi, const __nv_bfloat16* __restrict__ Alo,
    const __nv_bfloat16* __restrict__ Bhi, const __nv_bfloat16* __restrict__ Blo,
    const float* __restrict__ bias, float* __restrict__ C,
    __nv_bfloat16* __restrict__ Ohi, __nv_bfloat16* __restrict__ Olo,
    int K, int lda, int ldb, int ldc,
    long sA, long sB, long sC)
{
    extern __shared__ char sm[];
    const int z = blockIdx.z;
    Ahi += (size_t)z * sA; Alo += (size_t)z * sA;
    Bhi += (size_t)z * sB; Blo += (size_t)z * sB;
    C   += (size_t)z * sC;

    const int tid  = threadIdx.x;
    const int lane = tid & 31;
    const int warp = tid >> 5;
    const int wm   = warp >> 2;
    const int wn   = warp & 3;
    const int bm   = blockIdx.y * 128;
    const int bn   = blockIdx.x * 128;

    float acc[4][4][4];
#pragma unroll
    for (int i = 0; i < 4; i++)
#pragma unroll
        for (int j = 0; j < 4; j++)
#pragma unroll
            for (int c = 0; c < 4; c++) acc[i][j][c] = 0.0f;

    const int prow = tid >> 1;
    const int pk   = (tid & 1) << 4;
    const __nv_bfloat16* pAh = Ahi + (size_t)(bm + prow) * lda + pk;
    const __nv_bfloat16* pAl = Alo + (size_t)(bm + prow) * lda + pk;
    const __nv_bfloat16* pBh = Bhi + (size_t)(bn + prow) * ldb + pk;
    const __nv_bfloat16* pBl = Blo + (size_t)(bn + prow) * ldb + pk;

    const int swm  = ((prow >> 1) & 3) << 4;
    const int rowb = prow * 64;
    const int kb0  = (tid & 1) << 5;
    const int st0  = rowb + ((kb0 +  0) ^ swm);
    const int st1  = rowb + ((kb0 + 16) ^ swm);

    const unsigned smu = (unsigned)__cvta_generic_to_shared(sm);

#define ISSUE(sidx, bufi) do {                                                 \
        const int k0_ = (sidx) << 5;                                           \
        const unsigned b_ = smu + (bufi) * STG_SZ;                             \
        CPA(b_ + st0,            pAh + k0_);                                   \
        CPA(b_ + st1,            pAh + k0_ + 8);                               \
        CPA(b_ + A_LO_OFF + st0, pAl + k0_);                                   \
        CPA(b_ + A_LO_OFF + st1, pAl + k0_ + 8);                               \
        CPA(b_ + B_HI_OFF + st0, pBh + k0_);                                   \
        CPA(b_ + B_HI_OFF + st1, pBh + k0_ + 8);                               \
        CPA(b_ + B_LO_OFF + st0, pBl + k0_);                                   \
        CPA(b_ + B_LO_OFF + st1, pBl + k0_ + 8);                               \
    } while (0)

    const int nstage = K >> 5;

    ISSUE(0, 0);
    asm volatile("cp.async.commit_group;\n" ::: "memory");
    if (nstage > 1) ISSUE(1, 1);
    asm volatile("cp.async.commit_group;\n" ::: "memory");

    for (int s = 0; s < nstage; s++) {
        if (nstage > 1) asm volatile("cp.async.wait_group 1;\n" ::: "memory");
        else            asm volatile("cp.async.wait_group 0;\n" ::: "memory");
        __syncthreads();

        const unsigned stage = smu + (unsigned)((s % NSTAGES) * STG_SZ);
#pragma unroll
        for (int kk = 0; kk < 2; kk++) {
            unsigned Bhr[4][2], Blr[4][2];
#pragma unroll
            for (int np = 0; np < 2; np++) {
                const int row = wn * 32 + np * 16 + (lane & 7) + ((lane >> 4) << 3);
                const int kb  = kk * 32 + (((lane >> 3) & 1) << 4);
                const int off = row * 64 + (kb ^ (((row >> 1) & 3) << 4));
                unsigned r0, r1, r2, r3;
                LDSM4(r0, r1, r2, r3, stage + B_HI_OFF + off);
                Bhr[np * 2][0] = r0; Bhr[np * 2][1] = r1;
                Bhr[np * 2 + 1][0] = r2; Bhr[np * 2 + 1][1] = r3;
                LDSM4(r0, r1, r2, r3, stage + B_LO_OFF + off);
                Blr[np * 2][0] = r0; Blr[np * 2][1] = r1;
                Blr[np * 2 + 1][0] = r2; Blr[np * 2 + 1][1] = r3;
            }
#pragma unroll
            for (int mt = 0; mt < 4; mt++) {
                const int row = wm * 64 + mt * 16 + (lane & 15);
                const int kb  = kk * 32 + ((lane >> 4) << 4);
                const int off = row * 64 + (kb ^ (((row >> 1) & 3) << 4));
                unsigned Ahr[4], Alr[4];
                LDSM4(Ahr[0], Ahr[1], Ahr[2], Ahr[3], stage + off);
                LDSM4(Alr[0], Alr[1], Alr[2], Alr[3], stage + A_LO_OFF + off);
#pragma unroll
                for (int nt = 0; nt < 4; nt++) {
                    MMA16816(acc[mt][nt], Ahr, Bhr[nt]);
                    MMA16816(acc[mt][nt], Ahr, Blr[nt]);
                    MMA16816(acc[mt][nt], Alr, Bhr[nt]);
                }
            }
        }
        // NOTE: no second barrier — stage-s top sync already retired the
        // buffer ISSUE overwrites ((s+2)%3 == (s-1)%3).
        const int sn = s + NSTAGES - 1;
        if (sn < nstage) ISSUE(sn, sn % NSTAGES);
        asm volatile("cp.async.commit_group;\n" ::: "memory");
    }

    // epilogue
#pragma unroll
    for (int mt = 0; mt < 4; mt++) {
#pragma unroll
        for (int nt = 0; nt < 4; nt++) {
            const int row0 = bm + wm * 64 + mt * 16 + (lane >> 2);
            const int col0 = bn + wn * 32 + nt * 8 + ((lane & 3) << 1);
            float b0 = 0.f, b1 = 0.f;
            if (EPI == EPI_BIAS_SILU || EPI == EPI_BIAS_SOFTPLUS) {
                b0 = bias[col0]; b1 = bias[col0 + 1];
            }
#pragma unroll
            for (int half = 0; half < 2; half++) {
                const size_t row = (size_t)(row0 + half * 8);
                float2 v;
                v.x = epi_apply<EPI>(acc[mt][nt][2 * half + 0], b0);
                v.y = epi_apply<EPI>(acc[mt][nt][2 * half + 1], b1);
                *(float2*)(C + row * ldc + col0) = v;
                if (WS) {
                    __nv_bfloat16 hx, lx, hy, ly;
                    split1(v.x, hx, lx); split1(v.y, hy, ly);
                    __nv_bfloat162 hp; hp.x = hx; hp.y = hy;
                    __nv_bfloat162 lp; lp.x = lx; lp.y = ly;
                    *(unsigned*)(Ohi + row * ldc + col0) = *(unsigned*)&hp;
                    *(unsigned*)(Olo + row * ldc + col0) = *(unsigned*)&lp;
                }
            }
        }
    }
#undef ISSUE
}

// ===========================================================================
// Parallel depthwise causal conv (k=4) + bias + silu. One thread per (b,t,d4).
// ===========================================================================
__global__ void conv_silu_kernel(const float* __restrict__ xz,
                                 const float* __restrict__ w,
                                 const float* __restrict__ cb,
                                 float* __restrict__ xi,
                                 __nv_bfloat16* __restrict__ xih,
                                 __nv_bfloat16* __restrict__ xil)
{
    const int idx = blockIdx.x * blockDim.x + threadIdx.x;
    const int dq  = idx & 255;
    const int r   = idx >> 8;
    const int t   = r & 255;
    const int d4  = dq << 2;

    const float* base = xz + (size_t)r * 2048 + d4;
    const float4 zf = make_float4(0.f, 0.f, 0.f, 0.f);
    const float4 x3 = *(const float4*)base;
    const float4 x2 = (t >= 1) ? *(const float4*)(base - 2048) : zf;
    const float4 x1 = (t >= 2) ? *(const float4*)(base - 4096) : zf;
    const float4 x0 = (t >= 3) ? *(const float4*)(base - 6144) : zf;

    const float4 wa = *(const float4*)(w + (size_t)(d4 + 0) * 4);
    const float4 wb = *(const float4*)(w + (size_t)(d4 + 1) * 4);
    const float4 wc = *(const float4*)(w + (size_t)(d4 + 2) * 4);
    const float4 wd = *(const float4*)(w + (size_t)(d4 + 3) * 4);
    const float4 bi = *(const float4*)(cb + d4);

    float4 v;
    v.x = fmaf(wa.x, x0.x, fmaf(wa.y, x1.x, fmaf(wa.z, x2.x, fmaf(wa.w, x3.x, bi.x))));
    v.y = fmaf(wb.x, x0.y, fmaf(wb.y, x1.y, fmaf(wb.z, x2.y, fmaf(wb.w, x3.y, bi.y))));
    v.z = fmaf(wc.x, x0.z, fmaf(wc.y, x1.z, fmaf(wc.z, x2.z, fmaf(wc.w, x3.z, bi.z))));
    v.w = fmaf(wd.x, x0.w, fmaf(wd.y, x1.w, fmaf(wd.z, x2.w, fmaf(wd.w, x3.w, bi.w))));
    v.x = v.x / (1.0f + expf(-v.x));
    v.y = v.y / (1.0f + expf(-v.y));
    v.z = v.z / (1.0f + expf(-v.z));
    v.w = v.w / (1.0f + expf(-v.w));

    *(float4*)(xi + (size_t)r * DI + d4) = v;
    split_store4(v, xih, xil, (size_t)r * DI + d4);
}

// ===========================================================================
// Chunked selective scan (8 chunks of 32 steps).
// ===========================================================================
__global__ void scan_pass1(const float* __restrict__ dt,
                           const float* __restrict__ xi,
                           const float* __restrict__ dbl,
                           const float* __restrict__ Alog,
                           float* __restrict__ Sg,
                           float* __restrict__ q0g,
                           float* __restrict__ q1g)
{
    const int idx = blockIdx.x * blockDim.x + threadIdx.x;
    const int d = idx & (DI - 1);
    const int c = (idx >> 10) & (NCH - 1);
    const int b = idx >> 13;
    const float A0 = -expf(Alog[d * 2 + 0]);
    const float A1 = -expf(Alog[d * 2 + 1]);
    const int r0 = b * L_ + c * CHL;
    float S = 0.f, q0 = 0.f, q1 = 0.f;
#pragma unroll 4
    for (int t = 0; t < CHL; t++) {
        const size_t r = (size_t)(r0 + t);
        const float dtv = dt[r * DI + d];
        const float xv  = xi[r * DI + d];
        const float B0 = dbl[r * DBLP + DTR + 0];
        const float B1 = dbl[r * DBLP + DTR + 1];
        S += dtv;
        const float dx = dtv * xv;
        q0 = fmaf(expf(dtv * A0), q0, dx * B0);
        q1 = fmaf(expf(dtv * A1), q1, dx * B1);
    }
    Sg[idx] = S; q0g[idx] = q0; q1g[idx] = q1;
}

__global__ void scan_pass2(const float* __restrict__ Alog,
                           const float* __restrict__ Sg,
                           const float* __restrict__ q0g,
                           const float* __restrict__ q1g,
                           float* __restrict__ h0g,
                           float* __restrict__ h1g)
{
    const int tid = blockIdx.x * blockDim.x + threadIdx.x;
    const int d = tid & (DI - 1);
    const int b = tid >> 10;
    const float A0 = -expf(Alog[d * 2 + 0]);
    const float A1 = -expf(Alog[d * 2 + 1]);
    float h0 = 0.f, h1 = 0.f;
#pragma unroll
    for (int c = 0; c < NCH; c++) {
        const int i = ((b * NCH + c) << 10) + d;
        h0g[i] = h0; h1g[i] = h1;
        h0 = fmaf(expf(A0 * Sg[i]), h0, q0g[i]);
        h1 = fmaf(expf(A1 * Sg[i]), h1, q1g[i]);
    }
}

__global__ void scan_pass3(const float* __restrict__ dt,
                           const float* __restrict__ xi,
                           const float* __restrict__ dbl,
                           const float* __restrict__ xz,
                           const float* __restrict__ Alog,
                           const float* __restrict__ Dp,
                           const float* __restrict__ h0g,
                           const float* __restrict__ h1g,
                           __nv_bfloat16* __restrict__ yh,
                           __nv_bfloat16* __restrict__ yl)
{
    const int idx = blockIdx.x * blockDim.x + threadIdx.x;
    const int d = idx & (DI - 1);
    const int c = (idx >> 10) & (NCH - 1);
    const int b = idx >> 13;
    const float A0 = -expf(Alog[d * 2 + 0]);
    const float A1 = -expf(Alog[d * 2 + 1]);
    const float Dd = Dp[d];
    const int r0 = b * L_ + c * CHL;
    float h0 = h0g[idx], h1 = h1g[idx];
#pragma unroll 4
    for (int t = 0; t < CHL; t++) {
        const size_t r = (size_t)(r0 + t);
        const float dtv = dt[r * DI + d];
        const float xv  = xi[r * DI + d];
        const float zv  = xz[r * (2 * DI) + DI + d];
        const float B0 = dbl[r * DBLP + DTR + 0];
        const float B1 = dbl[r * DBLP + DTR + 1];
        const float C0 = dbl[r * DBLP + DTR + 2];
        const float C1 = dbl[r * DBLP + DTR + 3];
        const float dx = dtv * xv;
        h0 = fmaf(expf(dtv * A0), h0, dx * B0);
        h1 = fmaf(expf(dtv * A1), h1, dx * B1);
        float yv = fmaf(h0, C0, fmaf(h1, C1, Dd * xv));
        yv *= zv / (1.0f + expf(-zv));
        __nv_bfloat16 h, l;
        split1(yv, h, l);
        yh[r * DI + d] = h;
        yl[r * DI + d] = l;
    }
}

// ===========================================================================
// LayerNorm over last dim (1024), one block per row, eps = 1e-5.
// ===========================================================================
__global__ void ln_kernel(const float* __restrict__ in,
                          const float* __restrict__ g,
                          const float* __restrict__ bt,
                          float* __restrict__ out)
{
    const int row = blockIdx.x;
    const float* x = in  + (size_t)row * DM;
    float*       o = out + (size_t)row * DM;
    float v[4];
    float s = 0.f, s2 = 0.f;
#pragma unroll
    for (int i = 0; i < 4; i++) {
        v[i] = x[threadIdx.x + i * 256];
        s += v[i]; s2 += v[i] * v[i];
    }
#pragma unroll
    for (int off = 16; off > 0; off >>= 1) {
        s  += __shfl_down_sync(0xFFFFFFFFu, s,  off);
        s2 += __shfl_down_sync(0xFFFFFFFFu, s2, off);
    }
    __shared__ float rs[8], rs2[8];
    const int wid = threadIdx.x >> 5;
    if ((threadIdx.x & 31) == 0) { rs[wid] = s; rs2[wid] = s2; }
    __syncthreads();
    float ts = 0.f, ts2 = 0.f;
#pragma unroll
    for (int i = 0; i < 8; i++) { ts += rs[i]; ts2 += rs2[i]; }
    const float mean = ts * (1.0f / DM);
    const float var  = ts2 * (1.0f / DM) - mean * mean;
    const float inv  = rsqrtf(var + 1e-5f);
#pragma unroll
    for (int i = 0; i < 4; i++) {
        const int c = threadIdx.x + i * 256;
        o[c] = (v[i] - mean) * inv * g[c] + bt[c];
    }
}

__global__ void add_silu_kernel(const float* __restrict__ a,
                                const float* __restrict__ b,
                                float* __restrict__ o, int n)
{
    const int i = blockIdx.x * blockDim.x + threadIdx.x;
    if (i < n) {
        const float v = a[i] + b[i];
        o[i] = v / (1.0f + expf(-v));
    }
}

// ===========================================================================
// Host orchestration
// ===========================================================================
static inline void split_launch(const float* in, __nv_bfloat16* hi,
                                __nv_bfloat16* lo, int n) {
    split_kernel<<<(n / 4 + 255) / 256, 256>>>(in, hi, lo, n / 4);
}

struct Bufs {
    float *xz, *xi, *dblp, *dt, *bufA, *bufB, *bufC;
    float *S, *q0, *q1, *h0, *h1;
    __nv_bfloat16 *Xh, *Xl, *Ah, *Al, *Dh, *Dl, *WAh, *WAl;
};

static void run_mamba(const __nv_bfloat16* Inh, const __nv_bfloat16* Inl,
                      int owWin, int owWx, int owWdt, int owWout,
                      const float* convw, const float* convb,
                      const float* bdt, const float* Alog, const float* Dp,
                      float* out, const Bufs& B)
{
    // xz = x @ Win^T : [4096, 2048]
    gemm_sp<EPI_NONE, 0><<<dim3(16, 32), 256, MMA_SMEM>>>(
        Inh, Inl, B.WAh + owWin, B.WAl + owWin, nullptr, B.xz, nullptr, nullptr,
        DM, DM, DM, 2 * DI, 0, 0, 0);
    // xi = silu(conv + bias)  (+ fused split into Ah/Al)
    conv_silu_kernel<<<BL * DI / 4 / 256, 256>>>(B.xz, convw, convb, B.xi, B.Ah, B.Al);
    // dblp = xi @ WxPad^T : [4096, 128], K-split x4 (partials in g_dt scratch)
    gemm_sp<EPI_NONE, 0><<<dim3(1, 32, 4), 256, MMA_SMEM>>>(
        B.Ah, B.Al, B.WAh + owWx, B.WAl + owWx, nullptr, B.dt, nullptr, nullptr,
        DI / 4, DI, DI, DBLP, DI / 4, DI / 4, (long)BL * DBLP);
    reduce_wx_kernel<<<BL * DBLP / 4 / 256, 256>>>(B.dt, B.dblp, B.Dh, B.Dl);
    // dt = softplus(dblp[:, :64] @ Wdt^T + bdt) : [4096, 1024]
    gemm_sp<EPI_BIAS_SOFTPLUS, 0><<<dim3(8, 32), 256, MMA_SMEM>>>(
        B.Dh, B.Dl, B.WAh + owWdt, B.WAl + owWdt, bdt, B.dt, nullptr, nullptr,
        DTR, DBLP, DTR, DI, 0, 0, 0);
    // chunked scan (+ fused y split into Ah/Al)
    scan_pass1<<<B_ * NCH * DI / 256, 256>>>(B.dt, B.xi, B.dblp, Alog,
                                             B.S, B.q0, B.q1);
    scan_pass2<<<B_ * DI / 256, 256>>>(Alog, B.S, B.q0, B.q1, B.h0, B.h1);
    scan_pass3<<<B_ * NCH * DI / 256, 256>>>(B.dt, B.xi, B.dblp, B.xz, Alog, Dp,
                                             B.h0, B.h1, B.Ah, B.Al);
    // out = y @ Wout^T : [4096, 1024]
    gemm_sp<EPI_NONE, 0><<<dim3(8, 32), 256, MMA_SMEM>>>(
        B.Ah, B.Al, B.WAh + owWout, B.WAl + owWout, nullptr, out, nullptr, nullptr,
        DI, DI, DI, DM, 0, 0, 0);
}

extern "C" void kernel_launch(void* const* d_in, const int* in_sizes, int n_in,
                              void* d_out, int out_size)
{
    const float* x        = (const float*)d_in[0];
    const float* m1_Win   = (const float*)d_in[1];
    const float* m1_convw = (const float*)d_in[2];
    const float* m1_convb = (const float*)d_in[3];
    const float* m1_Wx    = (const float*)d_in[4];
    const float* m1_Wdt   = (const float*)d_in[5];
    const float* m1_bdt   = (const float*)d_in[6];
    const float* m1_Alog  = (const float*)d_in[7];
    const float* m1_D     = (const float*)d_in[8];
    const float* m1_Wout  = (const float*)d_in[9];
    const float* m2_Win   = (const float*)d_in[10];
    const float* m2_convw = (const float*)d_in[11];
    const float* m2_convb = (const float*)d_in[12];
    const float* m2_Wx    = (const float*)d_in[13];
    const float* m2_Wdt   = (const float*)d_in[14];
    const float* m2_bdt   = (const float*)d_in[15];
    const float* m2_Alog  = (const float*)d_in[16];
    const float* m2_D     = (const float*)d_in[17];
    const float* m2_Wout  = (const float*)d_in[18];
    const float* ln1_g    = (const float*)d_in[19];
    const float* ln1_b    = (const float*)d_in[20];
    const float* ln2_g    = (const float*)d_in[21];
    const float* ln2_b    = (const float*)d_in[22];
    const float* W_mid    = (const float*)d_in[23];
    const float* W_spa    = (const float*)d_in[24];
    const float* b_spa    = (const float*)d_in[25];
    const float* W_res    = (const float*)d_in[26];

    cudaFuncSetAttribute(gemm_sp<EPI_NONE, 0>,
                         cudaFuncAttributeMaxDynamicSharedMemorySize, MMA_SMEM);
    cudaFuncSetAttribute(gemm_sp<EPI_SILU, 0>,
                         cudaFuncAttributeMaxDynamicSharedMemorySize, MMA_SMEM);
    cudaFuncSetAttribute(gemm_sp<EPI_BIAS_SILU, 0>,
                         cudaFuncAttributeMaxDynamicSharedMemorySize, MMA_SMEM);
    cudaFuncSetAttribute(gemm_sp<EPI_BIAS_SOFTPLUS, 0>,
                         cudaFuncAttributeMaxDynamicSharedMemorySize, MMA_SMEM);

    Bufs B;
    cudaGetSymbolAddress((void**)&B.xz,   g_xz);
    cudaGetSymbolAddress((void**)&B.xi,   g_xi);
    cudaGetSymbolAddress((void**)&B.dblp, g_dblp);
    cudaGetSymbolAddress((void**)&B.dt,   g_dt);
    cudaGetSymbolAddress((void**)&B.bufA, g_bufA);
    cudaGetSymbolAddress((void**)&B.bufB, g_bufB);
    cudaGetSymbolAddress((void**)&B.bufC, g_bufC);
    cudaGetSymbolAddress((void**)&B.S,    g_S);
    cudaGetSymbolAddress((void**)&B.q0,   g_q0);
    cudaGetSymbolAddress((void**)&B.q1,   g_q1);
    cudaGetSymbolAddress((void**)&B.h0,   g_h0);
    cudaGetSymbolAddress((void**)&B.h1,   g_h1);
    cudaGetSymbolAddress((void**)&B.Xh,   g_Xh);
    cudaGetSymbolAddress((void**)&B.Xl,   g_Xl);
    cudaGetSymbolAddress((void**)&B.Ah,   g_Ah);
    cudaGetSymbolAddress((void**)&B.Al,   g_Al);
    cudaGetSymbolAddress((void**)&B.Dh,   g_Dh);
    cudaGetSymbolAddress((void**)&B.Dl,   g_Dl);
    cudaGetSymbolAddress((void**)&B.WAh,  g_WAh);
    cudaGetSymbolAddress((void**)&B.WAl,  g_WAl);

    // (1) split ALL weights once into the packed arena
    WSegArg S;
    S.src[0] = m1_Win;  S.src[1] = m1_Wx;  S.src[2] = m1_Wdt; S.src[3] = m1_Wout;
    S.src[4] = m2_Win;  S.src[5] = m2_Wx;  S.src[6] = m2_Wdt; S.src[7] = m2_Wout;
    S.src[8] = W_mid;   S.src[9] = W_spa;  S.src[10] = W_res;
    const int n4s[11] = {524288, 32768, 16384, 262144, 524288, 32768, 16384,
                         262144, 16384, 262144, 16384};
    int acc4 = 0;
    for (int k = 0; k < 11; k++) { acc4 += n4s[k]; S.cum4[k] = acc4; }
    wsplit_all_kernel<<<(OW_TOTAL / 4) / 256, 256>>>(S, B.WAh, B.WAl);

    // (2) split original x (reused by mamba1 and W_spa gemm)
    split_launch(x, B.Xh, B.Xl, BL * DM);

    // (3-5) r-branch first (independent): r = silu(W_res @ silu(x@W_spa^T+b))
    gemm_sp<EPI_BIAS_SILU, 0><<<dim3(8, 32), 256, MMA_SMEM>>>(
        B.Xh, B.Xl, B.WAh + OW_WSPA, B.WAl + OW_WSPA, b_spa, B.bufB,
        nullptr, nullptr, DM, DM, DM, DM, 0, 0, 0);
    transpose_split_kernel<<<dim3(32, 8, B_), dim3(32, 8)>>>(B.bufB, B.Ah, B.Al);
    gemm_sp<EPI_SILU, 0><<<dim3(8, 2, B_), 256, MMA_SMEM>>>(
        B.WAh + OW_WRES, B.WAl + OW_WRES, B.Ah, B.Al, nullptr, B.bufC,
        nullptr, nullptr, 256, 256, 256, 1024,
        0, (long)1024 * 256, (long)256 * 1024);

    // (6...) s = mamba1(x)   [launch #6 = Win GEMM -> ncu capture target]
    run_mamba(B.Xh, B.Xl, OW_WIN1, OW_WX1, OW_WDT1, OW_WOUT1,
              m1_convw, m1_convb, m1_bdt, m1_Alog, m1_D, B.bufA, B);
    // s = ln1(s)
    ln_kernel<<<BL, 256>>>(B.bufA, ln1_g, ln1_b, B.bufA);
    // s = silu(W_mid channel mix)
    transpose_split_kernel<<<dim3(32, 8, B_), dim3(32, 8)>>>(B.bufA, B.Ah, B.Al);
    gemm_sp<EPI_SILU, 0><<<dim3(8, 2, B_), 256, MMA_SMEM>>>(
        B.WAh + OW_WMID, B.WAl + OW_WMID, B.Ah, B.Al, nullptr, B.bufB,
        nullptr, nullptr, 256, 256, 256, 1024,
        0, (long)1024 * 256, (long)256 * 1024);
    // s = mamba2(s)
    split_launch(B.bufB, B.Ah, B.Al, BL * DM);
    run_mamba(B.Ah, B.Al, OW_WIN2, OW_WX2, OW_WDT2, OW_WOUT2,
              m2_convw, m2_convb, m2_bdt, m2_Alog, m2_D, B.bufA, B);
    // s = ln2(s)
    ln_kernel<<<BL, 256>>>(B.bufA, ln2_g, ln2_b, B.bufA);
    // out = silu(s + r)
    add_silu_kernel<<<(BL * DM) / 256, 256>>>(B.bufA, B.bufC, (float*)d_out, BL * DM);
}